// round 2
// baseline (speedup 1.0000x reference)
#include <cuda_runtime.h>
#include <math.h>

#define NU 8000
#define NI 10000
#define GG 4096

// ---- static scratch ----
__device__ float d_EV[(size_t)(NU + NI) * 72];
__device__ float d_OUTA[(size_t)2 * GG * 72];
__device__ float d_P[(size_t)2 * GG * 144];
__device__ float d_EY[(size_t)(NU + NI) * 144];
__device__ float d_MSG[(size_t)2 * GG * 144];
__device__ float d_GF[(size_t)GG * 128];
__device__ float d_invn[GG];
__device__ float d_iz[2 * GG];
__device__ float d_csum[2 * 8 * 64];
__device__ float d_rc[2 * 65];

__device__ __forceinline__ unsigned long long pk2(float a, float b) {
    unsigned long long r;
    asm("mov.b64 %0, {%1,%2};" : "=l"(r) : "f"(a), "f"(b));
    return r;
}
__device__ __forceinline__ void fma2(unsigned long long& d, unsigned long long a, unsigned long long b) {
    asm("fma.rn.f32x2 %0, %1, %2, %0;" : "+l"(d) : "l"(a), "l"(b));
}
__device__ __forceinline__ void mul2(unsigned long long& d, unsigned long long b) {
    asm("mul.rn.f32x2 %0, %0, %1;" : "+l"(d) : "l"(b));
}

// K1: partial column sums c_d = sum_n ws_n * X[n,d]
__global__ void k_colsum(const float* __restrict__ X, const float* __restrict__ uWs,
                         const float* __restrict__ iWs) {
    int part = blockIdx.y, slice = blockIdx.x;
    int Np = part ? NI : NU;
    int nstart = part ? NU : 0;
    const float* Ws = part ? iWs : uWs;
    int len = Np / 8;
    int d = threadIdx.x & 63, s = threadIdx.x >> 6;
    float acc = 0.f;
    int n_end = (slice + 1) * len;
    for (int n = slice * len + s; n < n_end; n += 4)
        acc += Ws[n] * X[(size_t)(nstart + n) * 64 + d];
    __shared__ float red[256];
    red[threadIdx.x] = acc;
    __syncthreads();
    if (s == 0)
        d_csum[(part * 8 + slice) * 64 + d] = red[d] + red[64 + d] + red[128 + d] + red[192 + d];
}

// K2: r vector + const per part
__global__ void k_prep(const float* uWq, const float* ubq, const float* uWk, const float* ubk,
                       const float* uWs, const float* ubs, const float* iWq, const float* ibq,
                       const float* iWk, const float* ibk, const float* iWs, const float* ibs) {
    int part = blockIdx.x;
    const float* Wq = part ? iWq : uWq; const float* bq = part ? ibq : ubq;
    const float* Wk = part ? iWk : uWk; const float* bk = part ? ibk : ubk;
    const float* Ws = part ? iWs : uWs; const float* bs = part ? ibs : ubs;
    int Np = part ? NI : NU;
    int t = threadIdx.x;
    __shared__ float cS[64], tS[64], sred[64];
    float c = 0.f;
    for (int sl = 0; sl < 8; sl++) c += d_csum[(part * 8 + sl) * 64 + t];
    cS[t] = c;
    float sp = 0.f;
    for (int n = t; n < Np; n += 64) sp += Ws[n];
    sred[t] = sp;
    __syncthreads();
    for (int off = 32; off > 0; off >>= 1) {
        if (t < off) sred[t] += sred[t + off];
        __syncthreads();
    }
    float S = sred[0];
    float th = bk[t] * S;
    for (int d = 0; d < 64; d++) th += Wk[t * 64 + d] * cS[d];
    tS[t] = th;
    __syncthreads();
    float r = 0.f;
    for (int h = 0; h < 64; h++) r += Wq[h * 64 + t] * tS[h];
    d_rc[part * 65 + t] = r;
    if (t == 0) {
        float cst = bs[0];
        for (int h = 0; h < 64; h++) cst += bq[h] * tS[h];
        d_rc[part * 65 + 64] = cst;
    }
}

// K3: per-row e, e^2, e*v
__global__ void __launch_bounds__(256) k_ev(const float* __restrict__ X, const float* uWv,
                                            const float* ubv, const float* iWv, const float* ibv) {
    int n0 = blockIdx.x * 4;
    int part = (n0 >= NU) ? 1 : 0;
    const float* Wv = part ? iWv : uWv;
    const float* bv = part ? ibv : ubv;
    __shared__ float xs[4][64];
    __shared__ float Wvs[64 * 65];
    __shared__ float rs[64];
    __shared__ float cstS;
    int t = threadIdx.x;
    {
        int nl = t >> 6, d = t & 63;
        xs[nl][d] = X[(size_t)(n0 + nl) * 64 + d];
    }
    for (int idx = t; idx < 4096; idx += 256) {
        int h = idx >> 6, d = idx & 63;
        Wvs[h * 65 + d] = Wv[idx];
    }
    if (t < 64) rs[t] = d_rc[part * 65 + t];
    if (t == 0) cstS = d_rc[part * 65 + 64];
    __syncthreads();
    int nl = t >> 6, h = t & 63;
    float s = cstS;
    for (int d = 0; d < 64; d++) s += xs[nl][d] * rs[d];
    float e = expf(s);
    float v = bv[h];
    for (int d = 0; d < 64; d++) v += xs[nl][d] * Wvs[h * 65 + d];
    size_t n = (size_t)(n0 + nl);
    d_EV[n * 72 + h] = e * v;
    if (h < 8) {
        float val = (h == 0) ? e : (h == 1) ? e * e : 0.f;
        d_EV[n * 72 + 64 + h] = val;
    }
}

// GEMM OUT[part] (G x NCPAD) = H_part^T @ B ; MODE 0: B=d_EV->d_OUTA, MODE 1: B=d_EY->d_MSG
template <int NCPAD, int TC, int MODE>
__global__ void __launch_bounds__(16 * (NCPAD / TC)) k_gemmHT(const int* __restrict__ H) {
    constexpr int NTHR = 16 * (NCPAD / TC);
    const float* B = (MODE == 0) ? d_EV : d_EY;
    float* OUT = (MODE == 0) ? d_OUTA : d_MSG;
    const int part = blockIdx.y;
    const int n0 = part ? NU : 0;
    const int cnt = part ? NI : NU;
    OUT += (size_t)part * GG * NCPAD;
    __shared__ __align__(16) float Hs[16][64];
    __shared__ __align__(16) float Bs[16][NCPAD];
    const int t = threadIdx.x;
    const int gx = t & 15, cy = t >> 4;
    const int g0 = blockIdx.x * 64;
    unsigned long long acc[4][TC / 2];
#pragma unroll
    for (int i = 0; i < 4; i++)
#pragma unroll
        for (int j = 0; j < TC / 2; j++) acc[i][j] = 0ull;
    const int nch = cnt / 16;
    for (int ck = 0; ck < nch; ck++) {
        int nb = n0 + ck * 16;
        for (int idx = t; idx < 256; idx += NTHR) {
            int r = idx >> 4, q = idx & 15;
            int4 h4 = *(const int4*)(H + (size_t)(nb + r) * GG + g0 + q * 4);
            *(float4*)&Hs[r][q * 4] =
                make_float4((float)h4.x, (float)h4.y, (float)h4.z, (float)h4.w);
        }
        constexpr int BV = NCPAD / 4;
        for (int idx = t; idx < 16 * BV; idx += NTHR) {
            int r = idx / BV, q = idx - r * BV;
            *(float4*)&Bs[r][q * 4] = *(const float4*)(B + (size_t)(nb + r) * NCPAD + q * 4);
        }
        __syncthreads();
#pragma unroll
        for (int k = 0; k < 16; k++) {
            float4 h4 = *(const float4*)&Hs[k][gx * 4];
            unsigned long long bp[TC / 2];
#pragma unroll
            for (int j = 0; j < TC / 2; j++)
                bp[j] = *(const unsigned long long*)&Bs[k][cy * TC + 2 * j];
            float hv[4] = {h4.x, h4.y, h4.z, h4.w};
#pragma unroll
            for (int i = 0; i < 4; i++) {
                unsigned long long h2 = pk2(hv[i], hv[i]);
#pragma unroll
                for (int j = 0; j < TC / 2; j++) fma2(acc[i][j], h2, bp[j]);
            }
        }
        __syncthreads();
    }
#pragma unroll
    for (int i = 0; i < 4; i++) {
        size_t row = (size_t)(g0 + gx * 4 + i);
#pragma unroll
        for (int j = 0; j < TC / 2; j++)
            *(unsigned long long*)&OUT[row * NCPAD + cy * TC + 2 * j] = acc[i][j];
    }
}

// K5: per-group Z, norms, gf, P
__global__ void k_groups() {
    int g = blockIdx.x * 256 + threadIdx.x;
    const float* A0 = d_OUTA + (size_t)g * 72;
    const float* A1 = d_OUTA + (size_t)(GG + g) * 72;
    float Zu = A0[64], S2u = A0[65], Zi = A1[64], S2i = A1[65];
    float izu = Zu > 0.f ? 1.f / Zu : 0.f;
    float izi = Zi > 0.f ? 1.f / Zi : 0.f;
    float n2 = S2u * izu * izu + S2i * izi * izi;
    float nn = sqrtf(n2);
    float invn = nn > 0.f ? 1.f / nn : 0.f;
    d_invn[g] = invn;
    d_iz[g] = izu;
    d_iz[GG + g] = izi;
    float* P0 = d_P + (size_t)g * 144;
    float* P1 = d_P + (size_t)(GG + g) * 144;
    for (int c = 0; c < 128; c++) {
        float gfc = (c < 64) ? A0[c] * izu : A1[c - 64] * izi;
        d_GF[(size_t)g * 128 + c] = gfc;
        P0[c] = gfc * invn * izu;
        P1[c] = gfc * invn * izi;
    }
    P0[128] = invn * izu;
    P1[128] = invn * izi;
    for (int c = 129; c < 144; c++) { P0[c] = 0.f; P1[c] = 0.f; }
}

// Pass B: EY = e^2 * (H_part @ P_part)
__global__ void __launch_bounds__(288) k_gemmHB(const int* __restrict__ H) {
    const int part = blockIdx.y;
    const int base = part ? NU : 0;
    const int cnt = part ? NI : NU;
    const float* P = d_P + (size_t)part * GG * 144;
    const int m0 = blockIdx.x * 64;
    if (m0 >= cnt) return;
    __shared__ __align__(16) float Hs[16][64];
    __shared__ __align__(16) float Ps[16][144];
    const int t = threadIdx.x;
    const int nx = t & 15, cy = t >> 4;
    unsigned long long acc[4][4];
#pragma unroll
    for (int i = 0; i < 4; i++)
#pragma unroll
        for (int j = 0; j < 4; j++) acc[i][j] = 0ull;
    for (int ck = 0; ck < GG / 16; ck++) {
        int k0 = ck * 16;
        if (t < 256) {
            int nl = t >> 2, q = t & 3;
            int4 h4 = make_int4(0, 0, 0, 0);
            int row = m0 + nl;
            if (row < cnt) h4 = *(const int4*)(H + (size_t)(base + row) * GG + k0 + q * 4);
            Hs[q * 4 + 0][nl] = (float)h4.x;
            Hs[q * 4 + 1][nl] = (float)h4.y;
            Hs[q * 4 + 2][nl] = (float)h4.z;
            Hs[q * 4 + 3][nl] = (float)h4.w;
        }
        for (int idx = t; idx < 16 * 36; idx += 288) {
            int r = idx / 36, q = idx - r * 36;
            *(float4*)&Ps[r][q * 4] = *(const float4*)(P + (size_t)(k0 + r) * 144 + q * 4);
        }
        __syncthreads();
#pragma unroll
        for (int k = 0; k < 16; k++) {
            float4 h4 = *(const float4*)&Hs[k][nx * 4];
            unsigned long long bp[4];
#pragma unroll
            for (int j = 0; j < 4; j++)
                bp[j] = *(const unsigned long long*)&Ps[k][cy * 8 + 2 * j];
            float hv[4] = {h4.x, h4.y, h4.z, h4.w};
#pragma unroll
            for (int i = 0; i < 4; i++) {
                unsigned long long h2 = pk2(hv[i], hv[i]);
#pragma unroll
                for (int j = 0; j < 4; j++) fma2(acc[i][j], h2, bp[j]);
            }
        }
        __syncthreads();
    }
#pragma unroll
    for (int i = 0; i < 4; i++) {
        int row = m0 + nx * 4 + i;
        if (row < cnt) {
            float e2 = d_EV[(size_t)(base + row) * 72 + 65];
            unsigned long long e2p = pk2(e2, e2);
#pragma unroll
            for (int j = 0; j < 4; j++) {
                unsigned long long vl = acc[i][j];
                mul2(vl, e2p);
                *(unsigned long long*)&d_EY[(size_t)(base + row) * 144 + cy * 8 + 2 * j] = vl;
            }
        }
    }
}

// K8: combine msg/deg, agg, final GEMM + sigmoid
__global__ void __launch_bounds__(256) k_final(const float* __restrict__ gW,
                                               const float* __restrict__ gb,
                                               float* __restrict__ out) {
    __shared__ float gWs[64][129];
    __shared__ float aggS[4][128];
    __shared__ float idegS[4];
    int t = threadIdx.x;
    int g0 = blockIdx.x * 4;
    for (int idx = t; idx < 8192; idx += 256) {
        int o = idx >> 7, c = idx & 127;
        gWs[o][c] = gW[idx];
    }
    if (t < 4) {
        int g = g0 + t;
        float inv = d_invn[g];
        float deg = inv * (d_iz[g] * d_MSG[(size_t)g * 144 + 128] +
                           d_iz[GG + g] * d_MSG[(size_t)(GG + g) * 144 + 128]);
        idegS[t] = deg > 0.f ? 1.f / deg : 0.f;
    }
    __syncthreads();
    for (int idx = t; idx < 512; idx += 256) {
        int gl = idx >> 7, c = idx & 127;
        int g = g0 + gl;
        float inv = d_invn[g];
        float msg = inv * (d_iz[g] * d_MSG[(size_t)g * 144 + c] +
                           d_iz[GG + g] * d_MSG[(size_t)(GG + g) * 144 + c]);
        float gf = d_GF[(size_t)g * 128 + c];
        aggS[gl][c] = 0.8f * gf + 0.2f * msg * idegS[gl];
    }
    __syncthreads();
    int gl = t >> 6, o = t & 63;
    float acc = gb[o];
#pragma unroll 8
    for (int c = 0; c < 128; c++) acc += aggS[gl][c] * gWs[o][c];
    out[(size_t)(g0 + gl) * 64 + o] = 1.f / (1.f + expf(-acc));
}

extern "C" void kernel_launch(void* const* d_in, const int* in_sizes, int n_in,
                              void* d_out, int out_size) {
    const int* H = (const int*)d_in[0];
    const float* X = (const float*)d_in[1];
    const float* uWq = (const float*)d_in[3];
    const float* ubq = (const float*)d_in[4];
    const float* uWk = (const float*)d_in[5];
    const float* ubk = (const float*)d_in[6];
    const float* uWv = (const float*)d_in[7];
    const float* ubv = (const float*)d_in[8];
    const float* uWs = (const float*)d_in[9];
    const float* ubs = (const float*)d_in[10];
    const float* iWq = (const float*)d_in[11];
    const float* ibq = (const float*)d_in[12];
    const float* iWk = (const float*)d_in[13];
    const float* ibk = (const float*)d_in[14];
    const float* iWv = (const float*)d_in[15];
    const float* ibv = (const float*)d_in[16];
    const float* iWs = (const float*)d_in[17];
    const float* ibs = (const float*)d_in[18];
    const float* gW = (const float*)d_in[19];
    const float* gb = (const float*)d_in[20];
    float* out = (float*)d_out;

    k_colsum<<<dim3(8, 2), 256>>>(X, uWs, iWs);
    k_prep<<<2, 64>>>(uWq, ubq, uWk, ubk, uWs, ubs, iWq, ibq, iWk, ibk, iWs, ibs);
    k_ev<<<(NU + NI) / 4, 256>>>(X, uWv, ubv, iWv, ibv);
    k_gemmHT<72, 8, 0><<<dim3(64, 2), 144>>>(H);
    k_groups<<<16, 256>>>();
    k_gemmHB<<<dim3(157, 2), 288>>>(H);
    k_gemmHT<144, 8, 1><<<dim3(64, 2), 288>>>(H);
    k_final<<<1024, 256>>>(gW, gb, out);
}

// round 4
// speedup vs baseline: 5.6870x; 5.6870x over previous
#include <cuda_runtime.h>
#include <cuda_bf16.h>
#include <stdint.h>
#include <math.h>

#define NU 8000
#define NI 10000
#define NT 18000
#define GG 4096
#define KCOLS 18048   // Ht/EVt/EYt columns: 8000 users + 10048 items (48 zero pad)
#define RPAD  18176   // Hbf rows: 8064 users + 10112 items

// ---------------- static scratch (zero-init at load; pads never written) ----------------
__device__ __nv_bfloat16 d_Hbf[(size_t)RPAD * GG];     // [n_pad][g]
__device__ __nv_bfloat16 d_Ht[(size_t)GG * KCOLS];     // [g][n_pad]
__device__ __nv_bfloat16 d_EVt[(size_t)80 * KCOLS];    // rows 0..63 e*v, 64 e, 65 e^2, 66..79 zero
__device__ __nv_bfloat16 d_EYt[(size_t)144 * KCOLS];   // rows 0..128 real, 129..143 zero
__device__ __nv_bfloat16 d_Pt[(size_t)2 * 144 * GG];   // [part][c][g], rows 129..143 zero
__device__ float d_e2f[RPAD];
__device__ float d_OUTAp[(size_t)16 * GG * 80];        // [split*2+part][g][80]
__device__ float d_MSGp[(size_t)16 * GG * 144];        // [split*2+part][g][144]
__device__ float d_GF[(size_t)GG * 128];
__device__ float d_invn[GG];
__device__ float d_iz[2 * GG];
__device__ float d_csum[2 * 8 * 64];
__device__ float d_rc[2 * 65];

// ---------------- helpers ----------------
__device__ __forceinline__ uint32_t s2u(const void* p) {
    uint32_t a;
    asm("{ .reg .u64 t; cvta.to.shared.u64 t, %1; cvt.u32.u64 %0, t; }" : "=r"(a) : "l"(p));
    return a;
}
#define LDSM4(r0, r1, r2, r3, addr)                                                  \
    asm volatile("ldmatrix.sync.aligned.m8n8.x4.shared.b16 {%0,%1,%2,%3}, [%4];"     \
                 : "=r"(r0), "=r"(r1), "=r"(r2), "=r"(r3)                            \
                 : "r"(addr))
#define LDSM2(r0, r1, addr)                                                          \
    asm volatile("ldmatrix.sync.aligned.m8n8.x2.shared.b16 {%0,%1}, [%2];"           \
                 : "=r"(r0), "=r"(r1)                                                \
                 : "r"(addr))
#define MMA16816(c0, c1, c2, c3, a0, a1, a2, a3, b0, b1)                             \
    asm volatile(                                                                    \
        "mma.sync.aligned.m16n8k16.row.col.f32.bf16.bf16.f32 "                       \
        "{%0,%1,%2,%3},{%4,%5,%6,%7},{%8,%9},{%0,%1,%2,%3};"                         \
        : "+f"(c0), "+f"(c1), "+f"(c2), "+f"(c3)                                     \
        : "r"(a0), "r"(a1), "r"(a2), "r"(a3), "r"(b0), "r"(b1))

// ---------------- K0: H -> bf16, both layouts ----------------
__global__ void __launch_bounds__(256) k_conv(const int* __restrict__ H) {
    __shared__ __nv_bfloat16 s[64][66];
    int g0 = blockIdx.x * 64, n0 = blockIdx.y * 64;
    int t = threadIdx.x;
#pragma unroll
    for (int i = 0; i < 16; i++) {
        int id = t + i * 256;
        int nl = id >> 6, gl = id & 63;
        int n = n0 + nl;
        __nv_bfloat16 v = __float2bfloat16(0.f);
        if (n < NT) {
            int hv = H[(size_t)n * GG + g0 + gl];
            v = __float2bfloat16((float)hv);
            int rp = n + (n >= NU ? 64 : 0);
            d_Hbf[(size_t)rp * GG + g0 + gl] = v;
        }
        s[nl][gl] = v;
    }
    __syncthreads();
#pragma unroll
    for (int i = 0; i < 16; i++) {
        int id = t + i * 256;
        int gl = id >> 6, nl = id & 63;
        d_Ht[(size_t)(g0 + gl) * KCOLS + n0 + nl] = s[nl][gl];
    }
}

// ---------------- K1: partial column sums ----------------
__global__ void k_colsum(const float* __restrict__ X, const float* __restrict__ uWs,
                         const float* __restrict__ iWs) {
    int part = blockIdx.y, slice = blockIdx.x;
    int Np = part ? NI : NU;
    int nstart = part ? NU : 0;
    const float* Ws = part ? iWs : uWs;
    int len = Np / 8;
    int d = threadIdx.x & 63, s = threadIdx.x >> 6;
    float acc = 0.f;
    int n_end = (slice + 1) * len;
    for (int n = slice * len + s; n < n_end; n += 4)
        acc += Ws[n] * X[(size_t)(nstart + n) * 64 + d];
    __shared__ float red[256];
    red[threadIdx.x] = acc;
    __syncthreads();
    if (s == 0)
        d_csum[(part * 8 + slice) * 64 + d] = red[d] + red[64 + d] + red[128 + d] + red[192 + d];
}

// ---------------- K2: r vector + const per part ----------------
__global__ void k_prep(const float* uWq, const float* ubq, const float* uWk, const float* ubk,
                       const float* uWs, const float* ubs, const float* iWq, const float* ibq,
                       const float* iWk, const float* ibk, const float* iWs, const float* ibs) {
    int part = blockIdx.x;
    const float* Wq = part ? iWq : uWq; const float* bq = part ? ibq : ubq;
    const float* Wk = part ? iWk : uWk; const float* bk = part ? ibk : ubk;
    const float* Ws = part ? iWs : uWs; const float* bs = part ? ibs : ubs;
    int Np = part ? NI : NU;
    int t = threadIdx.x;
    __shared__ float cS[64], tS[64], sred[64];
    float c = 0.f;
    for (int sl = 0; sl < 8; sl++) c += d_csum[(part * 8 + sl) * 64 + t];
    cS[t] = c;
    float sp = 0.f;
    for (int n = t; n < Np; n += 64) sp += Ws[n];
    sred[t] = sp;
    __syncthreads();
    for (int off = 32; off > 0; off >>= 1) {
        if (t < off) sred[t] += sred[t + off];
        __syncthreads();
    }
    float S = sred[0];
    float th = bk[t] * S;
    for (int d = 0; d < 64; d++) th += Wk[t * 64 + d] * cS[d];
    tS[t] = th;
    __syncthreads();
    float r = 0.f;
    for (int h = 0; h < 64; h++) r += Wq[h * 64 + t] * tS[h];
    d_rc[part * 65 + t] = r;
    if (t == 0) {
        float cst = bs[0];
        for (int h = 0; h < 64; h++) cst += bq[h] * tS[h];
        d_rc[part * 65 + 64] = cst;
    }
}

// ---------------- K3: per-row e, e^2, e*v (bf16 transposed out) ----------------
__global__ void __launch_bounds__(256) k_ev(const float* __restrict__ X, const float* uWv,
                                            const float* ubv, const float* iWv, const float* ibv) {
    int n0 = blockIdx.x * 4;
    int part = (n0 >= NU) ? 1 : 0;
    const float* Wv = part ? iWv : uWv;
    const float* bv = part ? ibv : ubv;
    __shared__ float xs[4][64];
    __shared__ float Wvs[64 * 65];
    __shared__ float rs[64];
    __shared__ float cstS;
    int t = threadIdx.x;
    {
        int nl = t >> 6, d = t & 63;
        xs[nl][d] = X[(size_t)(n0 + nl) * 64 + d];
    }
    for (int idx = t; idx < 4096; idx += 256) {
        int h = idx >> 6, d = idx & 63;
        Wvs[h * 65 + d] = Wv[idx];
    }
    if (t < 64) rs[t] = d_rc[part * 65 + t];
    if (t == 0) cstS = d_rc[part * 65 + 64];
    __syncthreads();
    int nl = t >> 6, h = t & 63;
    float s = cstS;
    for (int d = 0; d < 64; d++) s += xs[nl][d] * rs[d];
    float e = expf(s);
    float v = bv[h];
    for (int d = 0; d < 64; d++) v += xs[nl][d] * Wvs[h * 65 + d];
    size_t n = (size_t)(n0 + nl);
    d_EVt[(size_t)h * KCOLS + n] = __float2bfloat16(e * v);
    if (h == 0) {
        d_EVt[(size_t)64 * KCOLS + n] = __float2bfloat16(e);
        d_e2f[n + (part ? 64 : 0)] = e * e;
    }
    if (h == 1) d_EVt[(size_t)65 * KCOLS + n] = __float2bfloat16(e * e);
}

// ---------------- warp-level HMMA GEMM: C = A(MxK) * B(NxK)^T ----------------
// MODE 0: OUTAp[slot] = Ht-tile @ EVt^T   (M=4096, NCP=80, K split 8 per part)
// MODE 1: EYt = e2 * (Hbf @ Pt^T)         (M tiles of 64, NCP=144, K=4096)
// MODE 2: MSGp[slot] = Ht-tile @ EYt^T    (M=4096, NCP=144, K split 8 per part)
template <int MODE>
__global__ void __launch_bounds__(256) k_mma() {
    constexpr int NCP = (MODE == 0) ? 80 : 144;
    constexpr int MT = (MODE == 1) ? 64 : 128;
    constexpr int MW = MT / 4;     // warp rows
    constexpr int MSUB = MW / 16;  // 16-row subtiles per warp
    constexpr int NW = NCP / 2;    // warp cols
    constexpr int NSUB = NW / 8;   // 8-col subtiles per warp
    constexpr int SH_HALVES = (MODE == 1) ? 10368 : (MT * 40 + NCP * 40);

    __shared__ __align__(16) __nv_bfloat16 sh[SH_HALVES];
    __nv_bfloat16* As = sh;
    __nv_bfloat16* Bs = sh + MT * 40;

    const int t = threadIdx.x;
    const int lane = t & 31, warp = t >> 5;
    const int wm = warp & 3, wn = warp >> 2;
    const int mtile = blockIdx.x, split = blockIdx.y, part = blockIdx.z;
    if (MODE == 1 && part == 0 && mtile >= 125) return;

    const __nv_bfloat16 *A, *B;
    size_t Ast, Bst;
    int kc0, kc1;
    if (MODE == 1) {
        A = d_Hbf + (size_t)((part ? 8064 : 0) + mtile * 64) * GG;
        Ast = GG;
        B = d_Pt + (size_t)part * 144 * GG;
        Bst = GG;
        kc0 = 0; kc1 = 128;
    } else {
        int colbase = part ? 8000 : 0;
        A = d_Ht + (size_t)(mtile * 128) * KCOLS + colbase;
        Ast = KCOLS;
        B = ((MODE == 0) ? d_EVt : d_EYt) + colbase;
        Bst = KCOLS;
        int nch = part ? 314 : 250;
        int per = (nch + 7) / 8;
        kc0 = split * per;
        kc1 = kc0 + per;
        if (kc1 > nch) kc1 = nch;
    }

    float acc[MSUB][NSUB][4];
#pragma unroll
    for (int i = 0; i < MSUB; i++)
#pragma unroll
        for (int j = 0; j < NSUB; j++)
#pragma unroll
            for (int q = 0; q < 4; q++) acc[i][j][q] = 0.f;

    const uint32_t aBase = s2u(As), bBase = s2u(Bs);

    for (int kc = kc0; kc < kc1; kc++) {
        // load A tile: MT rows x 32 halves
#pragma unroll
        for (int i = 0; i < MT * 4 / 256; i++) {
            int id = t + i * 256;
            int r = id >> 2, c = id & 3;
            *(uint4*)(As + r * 40 + c * 8) = *(const uint4*)(A + (size_t)r * Ast + kc * 32 + c * 8);
        }
        // load B tile: NCP rows x 32 halves
#pragma unroll
        for (int i = 0; i < (NCP * 4 + 255) / 256; i++) {
            int id = t + i * 256;
            if ((NCP * 4) % 256 == 0 || id < NCP * 4) {
                int r = id >> 2, c = id & 3;
                *(uint4*)(Bs + r * 40 + c * 8) =
                    *(const uint4*)(B + (size_t)r * Bst + kc * 32 + c * 8);
            }
        }
        __syncthreads();
#pragma unroll
        for (int ks = 0; ks < 2; ks++) {
            uint32_t a[MSUB][4];
#pragma unroll
            for (int mi = 0; mi < MSUB; mi++) {
                uint32_t addr =
                    aBase + ((wm * MW + mi * 16 + (lane & 15)) * 40 + ks * 16 + (lane >> 4) * 8) * 2;
                LDSM4(a[mi][0], a[mi][1], a[mi][2], a[mi][3], addr);
            }
            uint32_t b[NSUB][2];
#pragma unroll
            for (int ni = 0; ni < NSUB; ni++) {
                uint32_t addr =
                    bBase + ((wn * NW + ni * 8 + (lane & 7)) * 40 + ks * 16 + ((lane >> 3) & 1) * 8) * 2;
                LDSM2(b[ni][0], b[ni][1], addr);
            }
#pragma unroll
            for (int mi = 0; mi < MSUB; mi++)
#pragma unroll
                for (int ni = 0; ni < NSUB; ni++)
                    MMA16816(acc[mi][ni][0], acc[mi][ni][1], acc[mi][ni][2], acc[mi][ni][3],
                             a[mi][0], a[mi][1], a[mi][2], a[mi][3], b[ni][0], b[ni][1]);
        }
        __syncthreads();
    }

    if (MODE != 1) {
        float* outp = ((MODE == 0) ? d_OUTAp : d_MSGp) + (size_t)(split * 2 + part) * GG * NCP;
#pragma unroll
        for (int mi = 0; mi < MSUB; mi++) {
            int gr = mtile * MT + wm * MW + mi * 16 + (lane >> 2);
#pragma unroll
            for (int ni = 0; ni < NSUB; ni++) {
                int col = wn * NW + ni * 8 + (lane & 3) * 2;
                *(float2*)&outp[(size_t)gr * NCP + col] =
                    make_float2(acc[mi][ni][0], acc[mi][ni][1]);
                *(float2*)&outp[(size_t)(gr + 8) * NCP + col] =
                    make_float2(acc[mi][ni][2], acc[mi][ni][3]);
            }
        }
    } else {
        // epilogue: *e2, bf16, transpose-store via smem stage [144][72]
        __nv_bfloat16* stage = sh;
        int partOff = part ? 8064 : 0;
        int rloc0 = wm * 16 + (lane >> 2);
        int rloc1 = rloc0 + 8;
        float e2a = d_e2f[partOff + mtile * 64 + rloc0];
        float e2b = d_e2f[partOff + mtile * 64 + rloc1];
#pragma unroll
        for (int ni = 0; ni < NSUB; ni++) {
            int col = wn * NW + ni * 8 + (lane & 3) * 2;
            stage[(col + 0) * 72 + rloc0] = __float2bfloat16(acc[0][ni][0] * e2a);
            stage[(col + 1) * 72 + rloc0] = __float2bfloat16(acc[0][ni][1] * e2a);
            stage[(col + 0) * 72 + rloc1] = __float2bfloat16(acc[0][ni][2] * e2b);
            stage[(col + 1) * 72 + rloc1] = __float2bfloat16(acc[0][ni][3] * e2b);
        }
        __syncthreads();
        int Np = part ? NI : NU;
        int colb = part ? 8000 : 0;
#pragma unroll
        for (int i = 0; i < 5; i++) {
            int id = t + i * 256;
            if (id < 144 * 8) {
                int r = id >> 3, q = id & 7;
                int nbase = mtile * 64 + q * 8;
                if (nbase + 8 <= Np) {
                    *(uint4*)(d_EYt + (size_t)r * KCOLS + colb + nbase) =
                        *(const uint4*)(stage + r * 72 + q * 8);
                } else if (nbase < Np) {
                    for (int e = 0; e < 8 && nbase + e < Np; e++)
                        d_EYt[(size_t)r * KCOLS + colb + nbase + e] = stage[r * 72 + q * 8 + e];
                }
            }
        }
    }
}

// ---------------- K5: reduce pass A, compute P / GF ----------------
__global__ void __launch_bounds__(256) k_groups() {
    __shared__ float sm[2][32][80];
    __shared__ float izS[2][32], invS[32];
    int t = threadIdx.x;
    int g0 = blockIdx.x * 32;
    for (int part = 0; part < 2; part++) {
        float r[10];
#pragma unroll
        for (int j = 0; j < 10; j++) r[j] = 0.f;
        for (int s = 0; s < 8; s++) {
            const float* base = d_OUTAp + ((size_t)(s * 2 + part) * GG + g0) * 80;
#pragma unroll
            for (int j = 0; j < 10; j++) r[j] += base[t + j * 256];
        }
#pragma unroll
        for (int j = 0; j < 10; j++) {
            int idx = t + j * 256;
            sm[part][idx / 80][idx % 80] = r[j];
        }
    }
    __syncthreads();
    if (t < 32) {
        int g = t;
        float Zu = sm[0][g][64], S2u = sm[0][g][65];
        float Zi = sm[1][g][64], S2i = sm[1][g][65];
        float izu = Zu > 0.f ? 1.f / Zu : 0.f;
        float izi = Zi > 0.f ? 1.f / Zi : 0.f;
        float n2 = S2u * izu * izu + S2i * izi * izi;
        float nn = sqrtf(n2);
        float invn = nn > 0.f ? 1.f / nn : 0.f;
        izS[0][g] = izu; izS[1][g] = izi; invS[g] = invn;
        d_iz[g0 + g] = izu; d_iz[GG + g0 + g] = izi; d_invn[g0 + g] = invn;
    }
    __syncthreads();
    for (int idx = t; idx < 32 * 129; idx += 256) {
        int g = idx & 31, c = idx >> 5;
        float gfc = 0.f;
        if (c < 128) {
            gfc = (c < 64) ? sm[0][g][c] * izS[0][g] : sm[1][g][c - 64] * izS[1][g];
            d_GF[(size_t)(g0 + g) * 128 + c] = gfc;
        }
        float inv = invS[g];
        float p0 = (c < 128) ? gfc * inv * izS[0][g] : inv * izS[0][g];
        float p1 = (c < 128) ? gfc * inv * izS[1][g] : inv * izS[1][g];
        d_Pt[(size_t)c * GG + g0 + g] = __float2bfloat16(p0);
        d_Pt[(size_t)(144 + c) * GG + g0 + g] = __float2bfloat16(p1);
    }
}

// ---------------- K8: combine, final GEMM + sigmoid ----------------
__global__ void __launch_bounds__(256) k_final(const float* __restrict__ gW,
                                               const float* __restrict__ gb,
                                               float* __restrict__ out) {
    __shared__ float gWs[64][129];
    __shared__ float aggS[4][128];
    __shared__ float idegS[4];
    int t = threadIdx.x;
    int g0 = blockIdx.x * 4;
    for (int idx = t; idx < 8192; idx += 256) gWs[idx >> 7][idx & 127] = gW[idx];
    if (t < 4) {
        int g = g0 + t;
        float mu = 0.f, mi = 0.f;
        for (int s = 0; s < 8; s++) {
            mu += d_MSGp[((size_t)(s * 2 + 0) * GG + g) * 144 + 128];
            mi += d_MSGp[((size_t)(s * 2 + 1) * GG + g) * 144 + 128];
        }
        float deg = d_invn[g] * (d_iz[g] * mu + d_iz[GG + g] * mi);
        idegS[t] = deg > 0.f ? 1.f / deg : 0.f;
    }
    __syncthreads();
    for (int idx = t; idx < 512; idx += 256) {
        int gl = idx >> 7, c = idx & 127;
        int g = g0 + gl;
        float mu = 0.f, mi = 0.f;
        for (int s = 0; s < 8; s++) {
            mu += d_MSGp[((size_t)(s * 2 + 0) * GG + g) * 144 + c];
            mi += d_MSGp[((size_t)(s * 2 + 1) * GG + g) * 144 + c];
        }
        float msg = d_invn[g] * (d_iz[g] * mu + d_iz[GG + g] * mi);
        float gf = d_GF[(size_t)g * 128 + c];
        aggS[gl][c] = 0.8f * gf + 0.2f * msg * idegS[gl];
    }
    __syncthreads();
    int gl = t >> 6, o = t & 63;
    float acc = gb[o];
#pragma unroll 8
    for (int c = 0; c < 128; c++) acc += aggS[gl][c] * gWs[o][c];
    out[(size_t)(g0 + gl) * 64 + o] = 1.f / (1.f + expf(-acc));
}

extern "C" void kernel_launch(void* const* d_in, const int* in_sizes, int n_in,
                              void* d_out, int out_size) {
    const int* H = (const int*)d_in[0];
    const float* X = (const float*)d_in[1];
    const float* uWq = (const float*)d_in[3];
    const float* ubq = (const float*)d_in[4];
    const float* uWk = (const float*)d_in[5];
    const float* ubk = (const float*)d_in[6];
    const float* uWv = (const float*)d_in[7];
    const float* ubv = (const float*)d_in[8];
    const float* uWs = (const float*)d_in[9];
    const float* ubs = (const float*)d_in[10];
    const float* iWq = (const float*)d_in[11];
    const float* ibq = (const float*)d_in[12];
    const float* iWk = (const float*)d_in[13];
    const float* ibk = (const float*)d_in[14];
    const float* iWv = (const float*)d_in[15];
    const float* ibv = (const float*)d_in[16];
    const float* iWs = (const float*)d_in[17];
    const float* ibs = (const float*)d_in[18];
    const float* gW = (const float*)d_in[19];
    const float* gb = (const float*)d_in[20];
    float* out = (float*)d_out;

    k_conv<<<dim3(64, 282), 256>>>(H);
    k_colsum<<<dim3(8, 2), 256>>>(X, uWs, iWs);
    k_prep<<<2, 64>>>(uWq, ubq, uWk, ubk, uWs, ubs, iWq, ibq, iWk, ibk, iWs, ibs);
    k_ev<<<(NU + NI) / 4, 256>>>(X, uWv, ubv, iWv, ibv);
    k_mma<0><<<dim3(32, 8, 2), 256>>>();
    k_groups<<<128, 256>>>();
    k_mma<1><<<dim3(157, 1, 2), 256>>>();
    k_mma<2><<<dim3(32, 8, 2), 256>>>();
    k_final<<<1024, 256>>>(gW, gb, out);
}

// round 5
// speedup vs baseline: 6.9768x; 1.2268x over previous
#include <cuda_runtime.h>
#include <cuda_bf16.h>
#include <stdint.h>
#include <math.h>

#define NU 8000
#define NI 10000
#define NT 18000
#define GG 4096
#define KCOLS 18048   // Ht/EVt/EYt columns: 8000 users + 10048 items (48 zero pad)

// ---------------- static scratch (zero-init at load; pads never written) ----------------
__device__ __nv_bfloat16 d_Ht[(size_t)GG * KCOLS];     // [g][n_pad]
__device__ __nv_bfloat16 d_EVt[(size_t)80 * KCOLS];    // rows 0..63 e*v, 64 e, 65 e^2, 66..79 zero
__device__ __nv_bfloat16 d_EYt[(size_t)144 * KCOLS];   // rows 0..128 real, 129..143 zero
__device__ __nv_bfloat16 d_Pt[(size_t)2 * 144 * GG];   // [part][c][g], rows 129..143 zero
__device__ float d_e2f[KCOLS];
__device__ float d_OUTAp[(size_t)16 * GG * 80];        // [split*2+part][g][80]
__device__ float d_MSGp[(size_t)16 * GG * 144];        // [split*2+part][g][144]
__device__ float d_GF[(size_t)GG * 128];
__device__ float d_invn[GG];
__device__ float d_iz[2 * GG];
__device__ float d_csum[2 * 8 * 64];
__device__ float d_rc[2 * 65];

// ---------------- helpers ----------------
__device__ __forceinline__ uint32_t s2u(const void* p) {
    uint32_t a;
    asm("{ .reg .u64 t; cvta.to.shared.u64 t, %1; cvt.u32.u64 %0, t; }" : "=r"(a) : "l"(p));
    return a;
}
#define LDSM4(r0, r1, r2, r3, addr)                                                  \
    asm volatile("ldmatrix.sync.aligned.m8n8.x4.shared.b16 {%0,%1,%2,%3}, [%4];"     \
                 : "=r"(r0), "=r"(r1), "=r"(r2), "=r"(r3)                            \
                 : "r"(addr))
#define LDSM4T(r0, r1, r2, r3, addr)                                                   \
    asm volatile("ldmatrix.sync.aligned.m8n8.x4.trans.shared.b16 {%0,%1,%2,%3}, [%4];" \
                 : "=r"(r0), "=r"(r1), "=r"(r2), "=r"(r3)                              \
                 : "r"(addr))
#define LDSM2(r0, r1, addr)                                                          \
    asm volatile("ldmatrix.sync.aligned.m8n8.x2.shared.b16 {%0,%1}, [%2];"           \
                 : "=r"(r0), "=r"(r1)                                                \
                 : "r"(addr))
#define MMA16816(c0, c1, c2, c3, a0, a1, a2, a3, b0, b1)                             \
    asm volatile(                                                                    \
        "mma.sync.aligned.m16n8k16.row.col.f32.bf16.bf16.f32 "                       \
        "{%0,%1,%2,%3},{%4,%5,%6,%7},{%8,%9},{%0,%1,%2,%3};"                         \
        : "+f"(c0), "+f"(c1), "+f"(c2), "+f"(c3)                                     \
        : "r"(a0), "r"(a1), "r"(a2), "r"(a3), "r"(b0), "r"(b1))

// ---------------- K0: H (int32) -> bf16 Ht [g][n] only ----------------
__global__ void __launch_bounds__(256) k_conv(const int* __restrict__ H) {
    __shared__ __nv_bfloat16 s[64][66];
    int g0 = blockIdx.x * 64, n0 = blockIdx.y * 64;
    int t = threadIdx.x;
#pragma unroll
    for (int i = 0; i < 4; i++) {
        int id = t + i * 256;
        int nl = id >> 4, gq = id & 15;
        int n = n0 + nl;
        __nv_bfloat16 z = __float2bfloat16(0.f);
        __nv_bfloat16 v0 = z, v1 = z, v2 = z, v3 = z;
        if (n < NT) {
            int4 h4 = *(const int4*)(H + (size_t)n * GG + g0 + gq * 4);
            v0 = __float2bfloat16((float)h4.x);
            v1 = __float2bfloat16((float)h4.y);
            v2 = __float2bfloat16((float)h4.z);
            v3 = __float2bfloat16((float)h4.w);
        }
        s[nl][gq * 4 + 0] = v0;
        s[nl][gq * 4 + 1] = v1;
        s[nl][gq * 4 + 2] = v2;
        s[nl][gq * 4 + 3] = v3;
    }
    __syncthreads();
#pragma unroll
    for (int i = 0; i < 2; i++) {
        int id = t + i * 256;
        int nq = id >> 6, gl = id & 63;
        __nv_bfloat16 tmp[8];
#pragma unroll
        for (int k = 0; k < 8; k++) tmp[k] = s[nq * 8 + k][gl];
        *(uint4*)(d_Ht + (size_t)(g0 + gl) * KCOLS + n0 + nq * 8) = *(const uint4*)tmp;
    }
}

// ---------------- K1: partial column sums ----------------
__global__ void k_colsum(const float* __restrict__ X, const float* __restrict__ uWs,
                         const float* __restrict__ iWs) {
    int part = blockIdx.y, slice = blockIdx.x;
    int Np = part ? NI : NU;
    int nstart = part ? NU : 0;
    const float* Ws = part ? iWs : uWs;
    int len = Np / 8;
    int d = threadIdx.x & 63, s = threadIdx.x >> 6;
    float acc = 0.f;
    int n_end = (slice + 1) * len;
    for (int n = slice * len + s; n < n_end; n += 4)
        acc += Ws[n] * X[(size_t)(nstart + n) * 64 + d];
    __shared__ float red[256];
    red[threadIdx.x] = acc;
    __syncthreads();
    if (s == 0)
        d_csum[(part * 8 + slice) * 64 + d] = red[d] + red[64 + d] + red[128 + d] + red[192 + d];
}

// ---------------- K2: r vector + const per part ----------------
__global__ void k_prep(const float* uWq, const float* ubq, const float* uWk, const float* ubk,
                       const float* uWs, const float* ubs, const float* iWq, const float* ibq,
                       const float* iWk, const float* ibk, const float* iWs, const float* ibs) {
    int part = blockIdx.x;
    const float* Wq = part ? iWq : uWq; const float* bq = part ? ibq : ubq;
    const float* Wk = part ? iWk : uWk; const float* bk = part ? ibk : ubk;
    const float* Ws = part ? iWs : uWs; const float* bs = part ? ibs : ubs;
    int Np = part ? NI : NU;
    int t = threadIdx.x;
    __shared__ float cS[64], tS[64], sred[64];
    float c = 0.f;
    for (int sl = 0; sl < 8; sl++) c += d_csum[(part * 8 + sl) * 64 + t];
    cS[t] = c;
    float sp = 0.f;
    for (int n = t; n < Np; n += 64) sp += Ws[n];
    sred[t] = sp;
    __syncthreads();
    for (int off = 32; off > 0; off >>= 1) {
        if (t < off) sred[t] += sred[t + off];
        __syncthreads();
    }
    float S = sred[0];
    float th = bk[t] * S;
    for (int d = 0; d < 64; d++) th += Wk[t * 64 + d] * cS[d];
    tS[t] = th;
    __syncthreads();
    float r = 0.f;
    for (int h = 0; h < 64; h++) r += Wq[h * 64 + t] * tS[h];
    d_rc[part * 65 + t] = r;
    if (t == 0) {
        float cst = bs[0];
        for (int h = 0; h < 64; h++) cst += bq[h] * tS[h];
        d_rc[part * 65 + 64] = cst;
    }
}

// ---------------- K3: per-row e, e^2, e*v — register-tiled, 80 rows/block ----------------
__global__ void __launch_bounds__(128) k_ev(const float* __restrict__ X, const float* uWv,
                                            const float* ubv, const float* iWv, const float* ibv) {
    __shared__ __align__(16) char shraw[(80 * 68 + 64 * 68) * 4];
    float* xs = (float*)shraw;        // [80][68]
    float* Wvs = xs + 80 * 68;        // [64][68]
    __shared__ float es[80], rs[64], bvs[64];
    __shared__ float cstS;
    int n0 = blockIdx.x * 80;
    int part = (n0 >= NU) ? 1 : 0;
    const float* Wv = part ? iWv : uWv;
    const float* bv = part ? ibv : ubv;
    int t = threadIdx.x;
#pragma unroll
    for (int i = 0; i < 10; i++) {
        int id = t + i * 128;
        int r = id >> 4, c4 = id & 15;
        *(float4*)&xs[r * 68 + c4 * 4] = *(const float4*)(X + (size_t)(n0 + r) * 64 + c4 * 4);
    }
#pragma unroll
    for (int i = 0; i < 8; i++) {
        int id = t + i * 128;
        int h = id >> 4, c4 = id & 15;
        *(float4*)&Wvs[h * 68 + c4 * 4] = *(const float4*)(Wv + h * 64 + c4 * 4);
    }
    if (t < 64) { rs[t] = d_rc[part * 65 + t]; bvs[t] = bv[t]; }
    if (t == 0) cstS = d_rc[part * 65 + 64];
    __syncthreads();
    if (t < 80) {
        float s = cstS;
#pragma unroll
        for (int d = 0; d < 64; d++) s += xs[t * 68 + d] * rs[d];
        es[t] = expf(s);
    }
    __syncthreads();
    int rg = t >> 3, hl = t & 7;
    float acc[5][8];
#pragma unroll
    for (int i = 0; i < 5; i++)
#pragma unroll
        for (int j = 0; j < 8; j++) acc[i][j] = 0.f;
#pragma unroll 4
    for (int d = 0; d < 64; d++) {
        float xv[5], wv[8];
#pragma unroll
        for (int i = 0; i < 5; i++) xv[i] = xs[(rg * 5 + i) * 68 + d];
#pragma unroll
        for (int j = 0; j < 8; j++) wv[j] = Wvs[(hl + 8 * j) * 68 + d];
#pragma unroll
        for (int i = 0; i < 5; i++)
#pragma unroll
            for (int j = 0; j < 8; j++) acc[i][j] += xv[i] * wv[j];
    }
    __syncthreads();  // xs dead; stage aliases it
    __nv_bfloat16* stage = (__nv_bfloat16*)shraw;  // [66][80]
#pragma unroll
    for (int i = 0; i < 5; i++) {
        int r = rg * 5 + i;
        float e = es[r];
#pragma unroll
        for (int j = 0; j < 8; j++) {
            int h = hl + 8 * j;
            stage[h * 80 + r] = __float2bfloat16(e * (acc[i][j] + bvs[h]));
        }
    }
    if (t < 80) {
        float e = es[t];
        stage[64 * 80 + t] = __float2bfloat16(e);
        stage[65 * 80 + t] = __float2bfloat16(e * e);
        d_e2f[n0 + t] = e * e;
    }
    __syncthreads();
#pragma unroll
    for (int i = 0; i < 6; i++) {
        int id = t + i * 128;
        if (id < 660) {
            int r = id / 10, q = id % 10;
            *(uint4*)(d_EVt + (size_t)r * KCOLS + n0 + q * 8) = *(const uint4*)(stage + r * 80 + q * 8);
        }
    }
}

// ---------------- pipelined HMMA GEMM ----------------
// MODE 0: OUTAp[slot] = Ht(128g x K) @ EVt(80 x K)^T   (K split 8 per part)
// MODE 1: EYt = e2 * (Ht^T(64n x 4096g) @ Pt(144 x 4096g)^T)  via ldmatrix.trans
// MODE 2: MSGp[slot] = Ht(64g x K) @ EYt(144 x K)^T    (K split 8 per part)
template <int MODE>
__global__ void __launch_bounds__(256) k_mma() {
    constexpr int NCP = (MODE == 0) ? 80 : 144;
    constexpr int MT = (MODE == 0) ? 128 : 64;
    constexpr int MW = MT / 4, MSUB = MW / 16, NW = NCP / 2, NSUB = NW / 8;
    constexpr int AITEMS = (MODE == 1) ? 256 : MT * 4;
    constexpr int BITEMS = NCP * 4;
    constexpr int AIT = (AITEMS + 255) / 256;
    constexpr int BIT = (BITEMS + 255) / 256;
    constexpr int SH = (MODE == 1) ? 10368 : (MT * 40 + NCP * 40);
    __shared__ __align__(16) __nv_bfloat16 sh[SH];
    __nv_bfloat16* As = sh;
    __nv_bfloat16* Bs = sh + ((MODE == 1) ? 32 * 72 : MT * 40);

    const int t = threadIdx.x, lane = t & 31, warp = t >> 5;
    const int wm = warp & 3, wn = warp >> 2;
    const int mtile = blockIdx.x, split = blockIdx.y, part = blockIdx.z;
    if (MODE == 1 && part == 0 && mtile >= 125) return;

    const __nv_bfloat16 *A, *B;
    size_t Ast, Bst;
    int kc0, kc1;
    if (MODE == 1) {
        A = d_Ht + mtile * 64;               Ast = KCOLS;
        B = d_Pt + (size_t)part * 144 * GG;  Bst = GG;
        kc0 = 0; kc1 = 128;
    } else {
        int colbase = part ? 8000 : 0;
        A = d_Ht + (size_t)(mtile * MT) * KCOLS + colbase; Ast = KCOLS;
        B = ((MODE == 0) ? d_EVt : d_EYt) + colbase;       Bst = KCOLS;
        int nch = part ? 314 : 250;
        int per = (nch + 7) >> 3;
        kc0 = split * per;
        kc1 = kc0 + per; if (kc1 > nch) kc1 = nch;
    }

    float acc[MSUB][NSUB][4];
#pragma unroll
    for (int i = 0; i < MSUB; i++)
#pragma unroll
        for (int j = 0; j < NSUB; j++)
#pragma unroll
            for (int q = 0; q < 4; q++) acc[i][j][q] = 0.f;

    uint4 pa[AIT], pb[BIT];
    {
        int kc = kc0;
#pragma unroll
        for (int i = 0; i < AIT; i++) {
            int id = t + i * 256;
            if (AITEMS % 256 == 0 || id < AITEMS) {
                if (MODE == 1) {
                    int r = id >> 3, c = id & 7;
                    pa[i] = *(const uint4*)(A + (size_t)(kc * 32 + r) * Ast + c * 8);
                } else {
                    int r = id >> 2, c = id & 3;
                    pa[i] = *(const uint4*)(A + (size_t)r * Ast + kc * 32 + c * 8);
                }
            }
        }
#pragma unroll
        for (int i = 0; i < BIT; i++) {
            int id = t + i * 256;
            if (BITEMS % 256 == 0 || id < BITEMS) {
                int r = id >> 2, c = id & 3;
                pb[i] = *(const uint4*)(B + (size_t)r * Bst + kc * 32 + c * 8);
            }
        }
    }

    const uint32_t aBase = s2u(As), bBase = s2u(Bs);
    for (int kc = kc0; kc < kc1; kc++) {
        // commit prefetched tile to smem
#pragma unroll
        for (int i = 0; i < AIT; i++) {
            int id = t + i * 256;
            if (AITEMS % 256 == 0 || id < AITEMS) {
                if (MODE == 1) {
                    int r = id >> 3, c = id & 7;
                    *(uint4*)(As + r * 72 + c * 8) = pa[i];
                } else {
                    int r = id >> 2, c = id & 3;
                    *(uint4*)(As + r * 40 + c * 8) = pa[i];
                }
            }
        }
#pragma unroll
        for (int i = 0; i < BIT; i++) {
            int id = t + i * 256;
            if (BITEMS % 256 == 0 || id < BITEMS) {
                int r = id >> 2, c = id & 3;
                *(uint4*)(Bs + r * 40 + c * 8) = pb[i];
            }
        }
        __syncthreads();
        // prefetch next tile (overlaps with mma below)
        if (kc + 1 < kc1) {
            int kn = kc + 1;
#pragma unroll
            for (int i = 0; i < AIT; i++) {
                int id = t + i * 256;
                if (AITEMS % 256 == 0 || id < AITEMS) {
                    if (MODE == 1) {
                        int r = id >> 3, c = id & 7;
                        pa[i] = *(const uint4*)(A + (size_t)(kn * 32 + r) * Ast + c * 8);
                    } else {
                        int r = id >> 2, c = id & 3;
                        pa[i] = *(const uint4*)(A + (size_t)r * Ast + kn * 32 + c * 8);
                    }
                }
            }
#pragma unroll
            for (int i = 0; i < BIT; i++) {
                int id = t + i * 256;
                if (BITEMS % 256 == 0 || id < BITEMS) {
                    int r = id >> 2, c = id & 3;
                    pb[i] = *(const uint4*)(B + (size_t)r * Bst + kn * 32 + c * 8);
                }
            }
        }
#pragma unroll
        for (int ks = 0; ks < 2; ks++) {
            uint32_t a[MSUB][4];
#pragma unroll
            for (int mi = 0; mi < MSUB; mi++) {
                if (MODE == 1) {
                    int krow = ks * 16 + ((lane >> 4) & 1) * 8 + (lane & 7);
                    int ncol = wm * 16 + ((lane >> 3) & 1) * 8;
                    uint32_t addr = aBase + (uint32_t)(krow * 72 + ncol) * 2;
                    LDSM4T(a[mi][0], a[mi][1], a[mi][2], a[mi][3], addr);
                } else {
                    uint32_t addr = aBase +
                        (uint32_t)((wm * MW + mi * 16 + (lane & 15)) * 40 + ks * 16 + (lane >> 4) * 8) * 2;
                    LDSM4(a[mi][0], a[mi][1], a[mi][2], a[mi][3], addr);
                }
            }
            uint32_t b[NSUB][2];
#pragma unroll
            for (int ni = 0; ni < NSUB; ni++) {
                uint32_t addr = bBase +
                    (uint32_t)((wn * NW + ni * 8 + (lane & 7)) * 40 + ks * 16 + ((lane >> 3) & 1) * 8) * 2;
                LDSM2(b[ni][0], b[ni][1], addr);
            }
#pragma unroll
            for (int mi = 0; mi < MSUB; mi++)
#pragma unroll
                for (int ni = 0; ni < NSUB; ni++)
                    MMA16816(acc[mi][ni][0], acc[mi][ni][1], acc[mi][ni][2], acc[mi][ni][3],
                             a[mi][0], a[mi][1], a[mi][2], a[mi][3], b[ni][0], b[ni][1]);
        }
        __syncthreads();
    }

    if (MODE != 1) {
        float* outp = ((MODE == 0) ? d_OUTAp : d_MSGp) + (size_t)(split * 2 + part) * GG * NCP;
#pragma unroll
        for (int mi = 0; mi < MSUB; mi++) {
            int gr = mtile * MT + wm * MW + mi * 16 + (lane >> 2);
#pragma unroll
            for (int ni = 0; ni < NSUB; ni++) {
                int col = wn * NW + ni * 8 + (lane & 3) * 2;
                *(float2*)&outp[(size_t)gr * NCP + col] = make_float2(acc[0 + mi][ni][0], acc[mi][ni][1]);
                *(float2*)&outp[(size_t)(gr + 8) * NCP + col] = make_float2(acc[mi][ni][2], acc[mi][ni][3]);
            }
        }
    } else {
        __nv_bfloat16* stage = sh;  // [144][72]
        int nbase_glob = (part ? 8000 : 0) + mtile * 64;
        int rloc0 = wm * 16 + (lane >> 2), rloc1 = rloc0 + 8;
        float e2a = d_e2f[nbase_glob + rloc0];
        float e2b = d_e2f[nbase_glob + rloc1];
#pragma unroll
        for (int ni = 0; ni < NSUB; ni++) {
            int col = wn * NW + ni * 8 + (lane & 3) * 2;
            stage[(col + 0) * 72 + rloc0] = __float2bfloat16(acc[0][ni][0] * e2a);
            stage[(col + 1) * 72 + rloc0] = __float2bfloat16(acc[0][ni][1] * e2a);
            stage[(col + 0) * 72 + rloc1] = __float2bfloat16(acc[0][ni][2] * e2b);
            stage[(col + 1) * 72 + rloc1] = __float2bfloat16(acc[0][ni][3] * e2b);
        }
        __syncthreads();
        int Np = part ? NI : NU;
        int colb = part ? 8000 : 0;
#pragma unroll
        for (int i = 0; i < 5; i++) {
            int id = t + i * 256;
            if (id < 144 * 8) {
                int r = id >> 3, q = id & 7;
                int nb = mtile * 64 + q * 8;
                if (nb + 8 <= Np) {
                    *(uint4*)(d_EYt + (size_t)r * KCOLS + colb + nb) = *(const uint4*)(stage + r * 72 + q * 8);
                } else if (nb < Np) {
                    for (int e = 0; e < 8 && nb + e < Np; e++)
                        d_EYt[(size_t)r * KCOLS + colb + nb + e] = stage[r * 72 + q * 8 + e];
                }
            }
        }
    }
}

// ---------------- K5: reduce pass A, compute P / GF ----------------
__global__ void __launch_bounds__(256) k_groups() {
    __shared__ float sm[2][32][80];
    __shared__ float izS[2][32], invS[32];
    int t = threadIdx.x;
    int g0 = blockIdx.x * 32;
    for (int part = 0; part < 2; part++) {
        float r[10];
#pragma unroll
        for (int j = 0; j < 10; j++) r[j] = 0.f;
        for (int s = 0; s < 8; s++) {
            const float* base = d_OUTAp + ((size_t)(s * 2 + part) * GG + g0) * 80;
#pragma unroll
            for (int j = 0; j < 10; j++) r[j] += base[t + j * 256];
        }
#pragma unroll
        for (int j = 0; j < 10; j++) {
            int idx = t + j * 256;
            sm[part][idx / 80][idx % 80] = r[j];
        }
    }
    __syncthreads();
    if (t < 32) {
        int g = t;
        float Zu = sm[0][g][64], S2u = sm[0][g][65];
        float Zi = sm[1][g][64], S2i = sm[1][g][65];
        float izu = Zu > 0.f ? 1.f / Zu : 0.f;
        float izi = Zi > 0.f ? 1.f / Zi : 0.f;
        float n2 = S2u * izu * izu + S2i * izi * izi;
        float nn = sqrtf(n2);
        float invn = nn > 0.f ? 1.f / nn : 0.f;
        izS[0][g] = izu; izS[1][g] = izi; invS[g] = invn;
        d_iz[g0 + g] = izu; d_iz[GG + g0 + g] = izi; d_invn[g0 + g] = invn;
    }
    __syncthreads();
    for (int idx = t; idx < 32 * 129; idx += 256) {
        int g = idx & 31, c = idx >> 5;
        float gfc = 0.f;
        if (c < 128) {
            gfc = (c < 64) ? sm[0][g][c] * izS[0][g] : sm[1][g][c - 64] * izS[1][g];
            d_GF[(size_t)(g0 + g) * 128 + c] = gfc;
        }
        float inv = invS[g];
        float p0 = (c < 128) ? gfc * inv * izS[0][g] : inv * izS[0][g];
        float p1 = (c < 128) ? gfc * inv * izS[1][g] : inv * izS[1][g];
        d_Pt[(size_t)c * GG + g0 + g] = __float2bfloat16(p0);
        d_Pt[(size_t)(144 + c) * GG + g0 + g] = __float2bfloat16(p1);
    }
}

// ---------------- K8: combine, final GEMM + sigmoid ----------------
__global__ void __launch_bounds__(256) k_final(const float* __restrict__ gW,
                                               const float* __restrict__ gb,
                                               float* __restrict__ out) {
    __shared__ float gWs[64][129];
    __shared__ float aggS[4][128];
    __shared__ float idegS[4];
    int t = threadIdx.x;
    int g0 = blockIdx.x * 4;
    for (int idx = t; idx < 8192; idx += 256) gWs[idx >> 7][idx & 127] = gW[idx];
    if (t < 4) {
        int g = g0 + t;
        float mu = 0.f, mi = 0.f;
        for (int s = 0; s < 8; s++) {
            mu += d_MSGp[((size_t)(s * 2 + 0) * GG + g) * 144 + 128];
            mi += d_MSGp[((size_t)(s * 2 + 1) * GG + g) * 144 + 128];
        }
        float deg = d_invn[g] * (d_iz[g] * mu + d_iz[GG + g] * mi);
        idegS[t] = deg > 0.f ? 1.f / deg : 0.f;
    }
    __syncthreads();
    for (int idx = t; idx < 512; idx += 256) {
        int gl = idx >> 7, c = idx & 127;
        int g = g0 + gl;
        float mu = 0.f, mi = 0.f;
        for (int s = 0; s < 8; s++) {
            mu += d_MSGp[((size_t)(s * 2 + 0) * GG + g) * 144 + c];
            mi += d_MSGp[((size_t)(s * 2 + 1) * GG + g) * 144 + c];
        }
        float msg = d_invn[g] * (d_iz[g] * mu + d_iz[GG + g] * mi);
        float gf = d_GF[(size_t)g * 128 + c];
        aggS[gl][c] = 0.8f * gf + 0.2f * msg * idegS[gl];
    }
    __syncthreads();
    int gl = t >> 6, o = t & 63;
    float acc = gb[o];
#pragma unroll 8
    for (int c = 0; c < 128; c++) acc += aggS[gl][c] * gWs[o][c];
    out[(size_t)(g0 + gl) * 64 + o] = 1.f / (1.f + expf(-acc));
}

extern "C" void kernel_launch(void* const* d_in, const int* in_sizes, int n_in,
                              void* d_out, int out_size) {
    const int* H = (const int*)d_in[0];
    const float* X = (const float*)d_in[1];
    const float* uWq = (const float*)d_in[3];
    const float* ubq = (const float*)d_in[4];
    const float* uWk = (const float*)d_in[5];
    const float* ubk = (const float*)d_in[6];
    const float* uWv = (const float*)d_in[7];
    const float* ubv = (const float*)d_in[8];
    const float* uWs = (const float*)d_in[9];
    const float* ubs = (const float*)d_in[10];
    const float* iWq = (const float*)d_in[11];
    const float* ibq = (const float*)d_in[12];
    const float* iWk = (const float*)d_in[13];
    const float* ibk = (const float*)d_in[14];
    const float* iWv = (const float*)d_in[15];
    const float* ibv = (const float*)d_in[16];
    const float* iWs = (const float*)d_in[17];
    const float* ibs = (const float*)d_in[18];
    const float* gW = (const float*)d_in[19];
    const float* gb = (const float*)d_in[20];
    float* out = (float*)d_out;

    k_conv<<<dim3(64, 282), 256>>>(H);
    k_colsum<<<dim3(8, 2), 256>>>(X, uWs, iWs);
    k_prep<<<2, 64>>>(uWq, ubq, uWk, ubk, uWs, ubs, iWq, ibq, iWk, ibk, iWs, ibs);
    k_ev<<<225, 128>>>(X, uWv, ubv, iWv, ibv);
    k_mma<0><<<dim3(32, 8, 2), 256>>>();
    k_groups<<<128, 256>>>();
    k_mma<1><<<dim3(157, 1, 2), 256>>>();
    k_mma<2><<<dim3(64, 8, 2), 256>>>();
    k_final<<<1024, 256>>>(gW, gb, out);
}

// round 6
// speedup vs baseline: 10.0170x; 1.4358x over previous
#include <cuda_runtime.h>
#include <cuda_bf16.h>
#include <stdint.h>
#include <math.h>

#define NU 8000
#define NI 10000
#define NT 18000
#define GG 4096
#define KCOLS 18048   // column count: 8000 users + 10048 items (48 zero pad)

// ---------------- static scratch (zero-init at load) ----------------
__device__ char d_Ht8[(size_t)GG * KCOLS];             // H^T as int8 [g][n_pad]
__device__ __nv_bfloat16 d_EVt[(size_t)80 * KCOLS];    // rows 0..63 e*v, 64 e, 65 e^2, 66..79 zero
__device__ __nv_bfloat16 d_EYt[(size_t)144 * KCOLS];   // rows 0..128 real, 129..143 zero
__device__ __nv_bfloat16 d_Pt[(size_t)2 * 144 * GG];   // [part][c][g], rows 129..143 zero
__device__ float d_e2f[KCOLS];
__device__ float d_OUTAp[(size_t)8 * GG * 80];         // [split*2+part][g][80]
__device__ float d_MSGp[(size_t)8 * GG * 144];         // [split*2+part][g][144]
__device__ float d_GF[(size_t)GG * 128];
__device__ float d_invn[GG];
__device__ float d_iz[2 * GG];
__device__ float d_csum[2 * 8 * 64];
__device__ float d_rc[2 * 65];

// ---------------- helpers ----------------
__device__ __forceinline__ uint32_t s2u(const void* p) {
    uint32_t a;
    asm("{ .reg .u64 t; cvta.to.shared.u64 t, %1; cvt.u32.u64 %0, t; }" : "=r"(a) : "l"(p));
    return a;
}
// int8{0,1} word (4 elems) -> two bf16x2 words
__device__ __forceinline__ void unp8(uint32_t w, uint32_t& lo, uint32_t& hi) {
    uint32_t a, b;
    asm("prmt.b32 %0, %1, 0, 0x4140;" : "=r"(a) : "r"(w));  // bytes {b0,0,b1,0}
    asm("prmt.b32 %0, %1, 0, 0x4342;" : "=r"(b) : "r"(w));  // bytes {b2,0,b3,0}
    lo = a * 0x3F80u;
    hi = b * 0x3F80u;
}
#define LDSM4(r0, r1, r2, r3, addr)                                                  \
    asm volatile("ldmatrix.sync.aligned.m8n8.x4.shared.b16 {%0,%1,%2,%3}, [%4];"     \
                 : "=r"(r0), "=r"(r1), "=r"(r2), "=r"(r3)                            \
                 : "r"(addr))
#define LDSM4T(r0, r1, r2, r3, addr)                                                   \
    asm volatile("ldmatrix.sync.aligned.m8n8.x4.trans.shared.b16 {%0,%1,%2,%3}, [%4];" \
                 : "=r"(r0), "=r"(r1), "=r"(r2), "=r"(r3)                              \
                 : "r"(addr))
#define LDSM2(r0, r1, addr)                                                          \
    asm volatile("ldmatrix.sync.aligned.m8n8.x2.shared.b16 {%0,%1}, [%2];"           \
                 : "=r"(r0), "=r"(r1)                                                \
                 : "r"(addr))
#define MMA16816(c0, c1, c2, c3, a0, a1, a2, a3, b0, b1)                             \
    asm volatile(                                                                    \
        "mma.sync.aligned.m16n8k16.row.col.f32.bf16.bf16.f32 "                       \
        "{%0,%1,%2,%3},{%4,%5,%6,%7},{%8,%9},{%0,%1,%2,%3};"                         \
        : "+f"(c0), "+f"(c1), "+f"(c2), "+f"(c3)                                     \
        : "r"(a0), "r"(a1), "r"(a2), "r"(a3), "r"(b0), "r"(b1))

// ---------------- K0: H (int32) -> int8 Ht8 [g][n] ----------------
__global__ void __launch_bounds__(256) k_conv(const int* __restrict__ H) {
    __shared__ char s[64][68];
    int g0 = blockIdx.x * 64, n0 = blockIdx.y * 64;
    int t = threadIdx.x;
#pragma unroll
    for (int i = 0; i < 4; i++) {
        int id = t + i * 256;
        int nl = id >> 4, gq = id & 15;
        int n = n0 + nl;
        char4 v = make_char4(0, 0, 0, 0);
        if (n < NT) {
            int4 h4 = *(const int4*)(H + (size_t)n * GG + g0 + gq * 4);
            v = make_char4((char)h4.x, (char)h4.y, (char)h4.z, (char)h4.w);
        }
        *(char4*)&s[nl][gq * 4] = v;
    }
    __syncthreads();
    int r = t >> 2, q = t & 3;
    char tmp[16];
#pragma unroll
    for (int k = 0; k < 16; k++) tmp[k] = s[q * 16 + k][r];
    *(uint4*)(d_Ht8 + (size_t)(g0 + r) * KCOLS + n0 + q * 16) = *(const uint4*)tmp;
}

// ---------------- K1: partial column sums ----------------
__global__ void k_colsum(const float* __restrict__ X, const float* __restrict__ uWs,
                         const float* __restrict__ iWs) {
    int part = blockIdx.y, slice = blockIdx.x;
    int Np = part ? NI : NU;
    int nstart = part ? NU : 0;
    const float* Ws = part ? iWs : uWs;
    int len = Np / 8;
    int d = threadIdx.x & 63, s = threadIdx.x >> 6;
    float acc = 0.f;
    int n_end = (slice + 1) * len;
    for (int n = slice * len + s; n < n_end; n += 4)
        acc += Ws[n] * X[(size_t)(nstart + n) * 64 + d];
    __shared__ float red[256];
    red[threadIdx.x] = acc;
    __syncthreads();
    if (s == 0)
        d_csum[(part * 8 + slice) * 64 + d] = red[d] + red[64 + d] + red[128 + d] + red[192 + d];
}

// ---------------- K2: r vector + const per part ----------------
__global__ void k_prep(const float* uWq, const float* ubq, const float* uWk, const float* ubk,
                       const float* uWs, const float* ubs, const float* iWq, const float* ibq,
                       const float* iWk, const float* ibk, const float* iWs, const float* ibs) {
    int part = blockIdx.x;
    const float* Wq = part ? iWq : uWq; const float* bq = part ? ibq : ubq;
    const float* Wk = part ? iWk : uWk; const float* bk = part ? ibk : ubk;
    const float* Ws = part ? iWs : uWs; const float* bs = part ? ibs : ubs;
    int Np = part ? NI : NU;
    int t = threadIdx.x;
    __shared__ float cS[64], tS[64], sred[64];
    float c = 0.f;
    for (int sl = 0; sl < 8; sl++) c += d_csum[(part * 8 + sl) * 64 + t];
    cS[t] = c;
    float sp = 0.f;
    for (int n = t; n < Np; n += 64) sp += Ws[n];
    sred[t] = sp;
    __syncthreads();
    for (int off = 32; off > 0; off >>= 1) {
        if (t < off) sred[t] += sred[t + off];
        __syncthreads();
    }
    float S = sred[0];
    float th = bk[t] * S;
    for (int d = 0; d < 64; d++) th += Wk[t * 64 + d] * cS[d];
    tS[t] = th;
    __syncthreads();
    float r = 0.f;
    for (int h = 0; h < 64; h++) r += Wq[h * 64 + t] * tS[h];
    d_rc[part * 65 + t] = r;
    if (t == 0) {
        float cst = bs[0];
        for (int h = 0; h < 64; h++) cst += bq[h] * tS[h];
        d_rc[part * 65 + 64] = cst;
    }
}

// ---------------- K3: per-row e, e^2, e*v ----------------
__global__ void __launch_bounds__(128) k_ev(const float* __restrict__ X, const float* uWv,
                                            const float* ubv, const float* iWv, const float* ibv) {
    __shared__ __align__(16) char shraw[(80 * 68 + 64 * 68) * 4];
    float* xs = (float*)shraw;        // [80][68]
    float* Wvs = xs + 80 * 68;        // [64][68]
    __shared__ float es[80], rs[64], bvs[64];
    __shared__ float cstS;
    int n0 = blockIdx.x * 80;
    int part = (n0 >= NU) ? 1 : 0;
    const float* Wv = part ? iWv : uWv;
    const float* bv = part ? ibv : ubv;
    int t = threadIdx.x;
#pragma unroll
    for (int i = 0; i < 10; i++) {
        int id = t + i * 128;
        int r = id >> 4, c4 = id & 15;
        *(float4*)&xs[r * 68 + c4 * 4] = *(const float4*)(X + (size_t)(n0 + r) * 64 + c4 * 4);
    }
#pragma unroll
    for (int i = 0; i < 8; i++) {
        int id = t + i * 128;
        int h = id >> 4, c4 = id & 15;
        *(float4*)&Wvs[h * 68 + c4 * 4] = *(const float4*)(Wv + h * 64 + c4 * 4);
    }
    if (t < 64) { rs[t] = d_rc[part * 65 + t]; bvs[t] = bv[t]; }
    if (t == 0) cstS = d_rc[part * 65 + 64];
    __syncthreads();
    if (t < 80) {
        float s = cstS;
#pragma unroll
        for (int d = 0; d < 64; d++) s += xs[t * 68 + d] * rs[d];
        es[t] = expf(s);
    }
    __syncthreads();
    int rg = t >> 3, hl = t & 7;
    float acc[5][8];
#pragma unroll
    for (int i = 0; i < 5; i++)
#pragma unroll
        for (int j = 0; j < 8; j++) acc[i][j] = 0.f;
#pragma unroll 4
    for (int d = 0; d < 64; d++) {
        float xv[5], wv[8];
#pragma unroll
        for (int i = 0; i < 5; i++) xv[i] = xs[(rg * 5 + i) * 68 + d];
#pragma unroll
        for (int j = 0; j < 8; j++) wv[j] = Wvs[(hl + 8 * j) * 68 + d];
#pragma unroll
        for (int i = 0; i < 5; i++)
#pragma unroll
            for (int j = 0; j < 8; j++) acc[i][j] += xv[i] * wv[j];
    }
    __syncthreads();
    __nv_bfloat16* stage = (__nv_bfloat16*)shraw;  // [66][80]
#pragma unroll
    for (int i = 0; i < 5; i++) {
        int r = rg * 5 + i;
        float e = es[r];
#pragma unroll
        for (int j = 0; j < 8; j++) {
            int h = hl + 8 * j;
            stage[h * 80 + r] = __float2bfloat16(e * (acc[i][j] + bvs[h]));
        }
    }
    if (t < 80) {
        float e = es[t];
        stage[64 * 80 + t] = __float2bfloat16(e);
        stage[65 * 80 + t] = __float2bfloat16(e * e);
        d_e2f[n0 + t] = e * e;
    }
    __syncthreads();
#pragma unroll
    for (int i = 0; i < 6; i++) {
        int id = t + i * 128;
        if (id < 660) {
            int r = id / 10, q = id % 10;
            *(uint4*)(d_EVt + (size_t)r * KCOLS + n0 + q * 8) = *(const uint4*)(stage + r * 80 + q * 8);
        }
    }
}

// ---------------- pipelined HMMA GEMM, K-tile 64, int8-A unpack ----------------
// MODE 0: OUTAp[slot] = Ht(128g x K) @ EVt(80 x K)^T   (K split 4 per part)
// MODE 1: EYt = e2 * (Ht^T(64n x 4096g) @ Pt(144 x 4096g)^T)  via ldmatrix.trans
// MODE 2: MSGp[slot] = Ht(64g x K) @ EYt(144 x K)^T    (K split 4 per part)
template <int MODE>
__global__ void __launch_bounds__(256) k_mma() {
    constexpr int NCP = (MODE == 0) ? 80 : 144;
    constexpr int MT = (MODE == 0) ? 128 : 64;
    constexpr int MW = MT / 4, MSUB = MW / 16, NW = NCP / 2, NSUB = NW / 8;
    constexpr int AROWS = (MODE == 0) ? 128 : 64;   // rows of int8 A tile (64 k-cols each)
    constexpr int AIT = AROWS * 4 / 256;            // 16B units per thread
    constexpr int BUNITS = NCP * 8;                 // 16B units (64 bf16 cols per row)
    constexpr int BIT = (BUNITS + 255) / 256;
    constexpr int SH = (AROWS + NCP) * 72;
    __shared__ __align__(16) __nv_bfloat16 sh[SH];
    __nv_bfloat16* As = sh;
    __nv_bfloat16* Bs = sh + AROWS * 72;

    const int t = threadIdx.x, lane = t & 31, warp = t >> 5;
    const int wm = warp & 3, wn = warp >> 2;
    const int mtile = blockIdx.x, split = blockIdx.y, part = blockIdx.z;
    if (MODE == 1 && part == 0 && mtile >= 125) return;

    const char* A8;
    const __nv_bfloat16* B;
    size_t Bst;
    int kc0, kc1;
    if (MODE == 1) {
        A8 = d_Ht8 + mtile * 64;
        B = d_Pt + (size_t)part * 144 * GG;
        Bst = GG;
        kc0 = 0; kc1 = 64;
    } else {
        int colbase = part ? 8000 : 0;
        A8 = d_Ht8 + (size_t)(mtile * MT) * KCOLS + colbase;
        B = ((MODE == 0) ? d_EVt : d_EYt) + colbase;
        Bst = KCOLS;
        int nch = part ? 157 : 125;
        int per = (nch + 3) >> 2;
        kc0 = split * per;
        kc1 = kc0 + per; if (kc1 > nch) kc1 = nch;
    }

    float acc[MSUB][NSUB][4];
#pragma unroll
    for (int i = 0; i < MSUB; i++)
#pragma unroll
        for (int j = 0; j < NSUB; j++)
#pragma unroll
            for (int q = 0; q < 4; q++) acc[i][j][q] = 0.f;

    uint4 pa[AIT], pb[BIT];
    {
        int kc = kc0;
#pragma unroll
        for (int i = 0; i < AIT; i++) {
            int id = t + i * 256;
            int r = id >> 2, c = id & 3;
            pa[i] = (MODE == 1)
                        ? *(const uint4*)(A8 + (size_t)(kc * 64 + r) * KCOLS + c * 16)
                        : *(const uint4*)(A8 + (size_t)r * KCOLS + kc * 64 + c * 16);
        }
#pragma unroll
        for (int i = 0; i < BIT; i++) {
            int id = t + i * 256;
            if (BUNITS % 256 == 0 || id < BUNITS) {
                int r = id >> 3, c = id & 7;
                pb[i] = *(const uint4*)(B + (size_t)r * Bst + kc * 64 + c * 8);
            }
        }
    }

    const uint32_t aBase = s2u(As), bBase = s2u(Bs);
    for (int kc = kc0; kc < kc1; kc++) {
        // commit prefetched tile (A: unpack int8 -> bf16)
#pragma unroll
        for (int i = 0; i < AIT; i++) {
            int id = t + i * 256;
            int r = id >> 2, c = id & 3;
            uint32_t w[8];
            unp8(pa[i].x, w[0], w[1]);
            unp8(pa[i].y, w[2], w[3]);
            unp8(pa[i].z, w[4], w[5]);
            unp8(pa[i].w, w[6], w[7]);
            uint4* dst = (uint4*)(As + r * 72 + c * 16);
            dst[0] = make_uint4(w[0], w[1], w[2], w[3]);
            dst[1] = make_uint4(w[4], w[5], w[6], w[7]);
        }
#pragma unroll
        for (int i = 0; i < BIT; i++) {
            int id = t + i * 256;
            if (BUNITS % 256 == 0 || id < BUNITS) {
                int r = id >> 3, c = id & 7;
                *(uint4*)(Bs + r * 72 + c * 8) = pb[i];
            }
        }
        __syncthreads();
        // prefetch next tile (overlaps mma below)
        if (kc + 1 < kc1) {
            int kn = kc + 1;
#pragma unroll
            for (int i = 0; i < AIT; i++) {
                int id = t + i * 256;
                int r = id >> 2, c = id & 3;
                pa[i] = (MODE == 1)
                            ? *(const uint4*)(A8 + (size_t)(kn * 64 + r) * KCOLS + c * 16)
                            : *(const uint4*)(A8 + (size_t)r * KCOLS + kn * 64 + c * 16);
            }
#pragma unroll
            for (int i = 0; i < BIT; i++) {
                int id = t + i * 256;
                if (BUNITS % 256 == 0 || id < BUNITS) {
                    int r = id >> 3, c = id & 7;
                    pb[i] = *(const uint4*)(B + (size_t)r * Bst + kn * 64 + c * 8);
                }
            }
        }
#pragma unroll
        for (int ks = 0; ks < 4; ks++) {
            uint32_t a[MSUB][4];
#pragma unroll
            for (int mi = 0; mi < MSUB; mi++) {
                if (MODE == 1) {
                    int krow = ks * 16 + ((lane >> 4) & 1) * 8 + (lane & 7);
                    int ncol = wm * 16 + ((lane >> 3) & 1) * 8;
                    uint32_t addr = aBase + (uint32_t)(krow * 72 + ncol) * 2;
                    LDSM4T(a[mi][0], a[mi][1], a[mi][2], a[mi][3], addr);
                } else {
                    uint32_t addr = aBase +
                        (uint32_t)((wm * MW + mi * 16 + (lane & 15)) * 72 + ks * 16 + (lane >> 4) * 8) * 2;
                    LDSM4(a[mi][0], a[mi][1], a[mi][2], a[mi][3], addr);
                }
            }
            uint32_t b[NSUB][2];
#pragma unroll
            for (int np = 0; np < NSUB / 2; np++) {
                int base = wn * NW + np * 16;
                uint32_t addr = bBase +
                    (uint32_t)((base + ((lane >> 4) & 1) * 8 + (lane & 7)) * 72 + ks * 16 +
                               ((lane >> 3) & 1) * 8) * 2;
                LDSM4(b[2 * np][0], b[2 * np][1], b[2 * np + 1][0], b[2 * np + 1][1], addr);
            }
            if (NSUB & 1) {
                int ni = NSUB - 1;
                uint32_t addr = bBase +
                    (uint32_t)((wn * NW + ni * 8 + (lane & 7)) * 72 + ks * 16 +
                               ((lane >> 3) & 1) * 8) * 2;
                LDSM2(b[ni][0], b[ni][1], addr);
            }
#pragma unroll
            for (int mi = 0; mi < MSUB; mi++)
#pragma unroll
                for (int ni = 0; ni < NSUB; ni++)
                    MMA16816(acc[mi][ni][0], acc[mi][ni][1], acc[mi][ni][2], acc[mi][ni][3],
                             a[mi][0], a[mi][1], a[mi][2], a[mi][3], b[ni][0], b[ni][1]);
        }
        __syncthreads();
    }

    if (MODE != 1) {
        float* outp = ((MODE == 0) ? d_OUTAp : d_MSGp) + (size_t)(split * 2 + part) * GG * NCP;
#pragma unroll
        for (int mi = 0; mi < MSUB; mi++) {
            int gr = mtile * MT + wm * MW + mi * 16 + (lane >> 2);
#pragma unroll
            for (int ni = 0; ni < NSUB; ni++) {
                int col = wn * NW + ni * 8 + (lane & 3) * 2;
                *(float2*)&outp[(size_t)gr * NCP + col] = make_float2(acc[mi][ni][0], acc[mi][ni][1]);
                *(float2*)&outp[(size_t)(gr + 8) * NCP + col] = make_float2(acc[mi][ni][2], acc[mi][ni][3]);
            }
        }
    } else {
        __nv_bfloat16* stage = sh;  // [144][72]
        int nbase_glob = (part ? 8000 : 0) + mtile * 64;
        int rloc0 = wm * 16 + (lane >> 2), rloc1 = rloc0 + 8;
        float e2a = d_e2f[nbase_glob + rloc0];
        float e2b = d_e2f[nbase_glob + rloc1];
#pragma unroll
        for (int ni = 0; ni < NSUB; ni++) {
            int col = wn * NW + ni * 8 + (lane & 3) * 2;
            stage[(col + 0) * 72 + rloc0] = __float2bfloat16(acc[0][ni][0] * e2a);
            stage[(col + 1) * 72 + rloc0] = __float2bfloat16(acc[0][ni][1] * e2a);
            stage[(col + 0) * 72 + rloc1] = __float2bfloat16(acc[0][ni][2] * e2b);
            stage[(col + 1) * 72 + rloc1] = __float2bfloat16(acc[0][ni][3] * e2b);
        }
        __syncthreads();
        int Np = part ? NI : NU;
        int colb = part ? 8000 : 0;
#pragma unroll
        for (int i = 0; i < 5; i++) {
            int id = t + i * 256;
            if (id < 144 * 8) {
                int r = id >> 3, q = id & 7;
                int nb = mtile * 64 + q * 8;
                if (nb + 8 <= Np) {
                    *(uint4*)(d_EYt + (size_t)r * KCOLS + colb + nb) = *(const uint4*)(stage + r * 72 + q * 8);
                } else if (nb < Np) {
                    for (int e = 0; e < 8 && nb + e < Np; e++)
                        d_EYt[(size_t)r * KCOLS + colb + nb + e] = stage[r * 72 + q * 8 + e];
                }
            }
        }
    }
}

// ---------------- K5: reduce pass A, compute P / GF ----------------
__global__ void __launch_bounds__(256) k_groups() {
    __shared__ float sm[2][32][80];
    __shared__ float izS[2][32], invS[32];
    int t = threadIdx.x;
    int g0 = blockIdx.x * 32;
    for (int part = 0; part < 2; part++) {
        float r[10];
#pragma unroll
        for (int j = 0; j < 10; j++) r[j] = 0.f;
        for (int s = 0; s < 4; s++) {
            const float* base = d_OUTAp + ((size_t)(s * 2 + part) * GG + g0) * 80;
#pragma unroll
            for (int j = 0; j < 10; j++) r[j] += base[t + j * 256];
        }
#pragma unroll
        for (int j = 0; j < 10; j++) {
            int idx = t + j * 256;
            sm[part][idx / 80][idx % 80] = r[j];
        }
    }
    __syncthreads();
    if (t < 32) {
        int g = t;
        float Zu = sm[0][g][64], S2u = sm[0][g][65];
        float Zi = sm[1][g][64], S2i = sm[1][g][65];
        float izu = Zu > 0.f ? 1.f / Zu : 0.f;
        float izi = Zi > 0.f ? 1.f / Zi : 0.f;
        float n2 = S2u * izu * izu + S2i * izi * izi;
        float nn = sqrtf(n2);
        float invn = nn > 0.f ? 1.f / nn : 0.f;
        izS[0][g] = izu; izS[1][g] = izi; invS[g] = invn;
        d_iz[g0 + g] = izu; d_iz[GG + g0 + g] = izi; d_invn[g0 + g] = invn;
    }
    __syncthreads();
    for (int idx = t; idx < 32 * 129; idx += 256) {
        int g = idx & 31, c = idx >> 5;
        float gfc = 0.f;
        if (c < 128) {
            gfc = (c < 64) ? sm[0][g][c] * izS[0][g] : sm[1][g][c - 64] * izS[1][g];
            d_GF[(size_t)(g0 + g) * 128 + c] = gfc;
        }
        float inv = invS[g];
        float p0 = (c < 128) ? gfc * inv * izS[0][g] : inv * izS[0][g];
        float p1 = (c < 128) ? gfc * inv * izS[1][g] : inv * izS[1][g];
        d_Pt[(size_t)c * GG + g0 + g] = __float2bfloat16(p0);
        d_Pt[(size_t)(144 + c) * GG + g0 + g] = __float2bfloat16(p1);
    }
}

// ---------------- K8: combine, final GEMM + sigmoid ----------------
__global__ void __launch_bounds__(256) k_final(const float* __restrict__ gW,
                                               const float* __restrict__ gb,
                                               float* __restrict__ out) {
    __shared__ float gWs[64][129];
    __shared__ float aggS[4][128];
    __shared__ float idegS[4];
    int t = threadIdx.x;
    int g0 = blockIdx.x * 4;
    for (int idx = t; idx < 8192; idx += 256) gWs[idx >> 7][idx & 127] = gW[idx];
    if (t < 4) {
        int g = g0 + t;
        float mu = 0.f, mi = 0.f;
        for (int s = 0; s < 4; s++) {
            mu += d_MSGp[((size_t)(s * 2 + 0) * GG + g) * 144 + 128];
            mi += d_MSGp[((size_t)(s * 2 + 1) * GG + g) * 144 + 128];
        }
        float deg = d_invn[g] * (d_iz[g] * mu + d_iz[GG + g] * mi);
        idegS[t] = deg > 0.f ? 1.f / deg : 0.f;
    }
    __syncthreads();
    for (int idx = t; idx < 512; idx += 256) {
        int gl = idx >> 7, c = idx & 127;
        int g = g0 + gl;
        float mu = 0.f, mi = 0.f;
        for (int s = 0; s < 4; s++) {
            mu += d_MSGp[((size_t)(s * 2 + 0) * GG + g) * 144 + c];
            mi += d_MSGp[((size_t)(s * 2 + 1) * GG + g) * 144 + c];
        }
        float msg = d_invn[g] * (d_iz[g] * mu + d_iz[GG + g] * mi);
        float gf = d_GF[(size_t)g * 128 + c];
        aggS[gl][c] = 0.8f * gf + 0.2f * msg * idegS[gl];
    }
    __syncthreads();
    int gl = t >> 6, o = t & 63;
    float acc = gb[o];
#pragma unroll 8
    for (int c = 0; c < 128; c++) acc += aggS[gl][c] * gWs[o][c];
    out[(size_t)(g0 + gl) * 64 + o] = 1.f / (1.f + expf(-acc));
}

extern "C" void kernel_launch(void* const* d_in, const int* in_sizes, int n_in,
                              void* d_out, int out_size) {
    const int* H = (const int*)d_in[0];
    const float* X = (const float*)d_in[1];
    const float* uWq = (const float*)d_in[3];
    const float* ubq = (const float*)d_in[4];
    const float* uWk = (const float*)d_in[5];
    const float* ubk = (const float*)d_in[6];
    const float* uWv = (const float*)d_in[7];
    const float* ubv = (const float*)d_in[8];
    const float* uWs = (const float*)d_in[9];
    const float* ubs = (const float*)d_in[10];
    const float* iWq = (const float*)d_in[11];
    const float* ibq = (const float*)d_in[12];
    const float* iWk = (const float*)d_in[13];
    const float* ibk = (const float*)d_in[14];
    const float* iWv = (const float*)d_in[15];
    const float* ibv = (const float*)d_in[16];
    const float* iWs = (const float*)d_in[17];
    const float* ibs = (const float*)d_in[18];
    const float* gW = (const float*)d_in[19];
    const float* gb = (const float*)d_in[20];
    float* out = (float*)d_out;

    k_conv<<<dim3(64, 282), 256>>>(H);
    k_colsum<<<dim3(8, 2), 256>>>(X, uWs, iWs);
    k_prep<<<2, 64>>>(uWq, ubq, uWk, ubk, uWs, ubs, iWq, ibq, iWk, ibk, iWs, ibs);
    k_ev<<<225, 128>>>(X, uWv, ubv, iWv, ibv);
    k_mma<0><<<dim3(32, 4, 2), 256>>>();
    k_groups<<<128, 256>>>();
    k_mma<1><<<dim3(157, 1, 2), 256>>>();
    k_mma<2><<<dim3(64, 4, 2), 256>>>();
    k_final<<<1024, 256>>>(gW, gb, out);
}

// round 7
// speedup vs baseline: 10.6220x; 1.0604x over previous
#include <cuda_runtime.h>
#include <cuda_bf16.h>
#include <stdint.h>
#include <math.h>

#define NU 8000
#define NI 10000
#define NT 18000
#define GG 4096
#define KCOLS 18048   // column count: 8000 users + 10048 items (48 zero pad)

// ---------------- static scratch (zero-init at load) ----------------
__device__ char d_Ht8[(size_t)GG * KCOLS];             // H^T as int8 [g][n_pad]
__device__ __nv_bfloat16 d_EVt[(size_t)80 * KCOLS];    // rows 0..63 e*v, 64 e, 65 e^2, 66..79 zero
__device__ __nv_bfloat16 d_EYt[(size_t)144 * KCOLS];   // rows 0..128 real, 129..143 zero
__device__ __nv_bfloat16 d_Pt[(size_t)2 * 144 * GG];   // [part][c][g], rows 129..143 zero
__device__ float d_e2f[KCOLS];
__device__ float d_OUTAp[(size_t)8 * GG * 80];         // [split*2+part][g][80]
__device__ float d_MSGp[(size_t)8 * GG * 144];         // [split*2+part][g][144]
__device__ float d_GF[(size_t)GG * 128];
__device__ float d_invn[GG];
__device__ float d_iz[2 * GG];
__device__ float d_csum[2 * 8 * 64];
__device__ float d_rc[2 * 65];

// ---------------- helpers ----------------
__device__ __forceinline__ uint32_t s2u(const void* p) {
    uint32_t a;
    asm("{ .reg .u64 t; cvta.to.shared.u64 t, %1; cvt.u32.u64 %0, t; }" : "=r"(a) : "l"(p));
    return a;
}
// int8{0,1} word (4 elems) -> two bf16x2 words
__device__ __forceinline__ void unp8(uint32_t w, uint32_t& lo, uint32_t& hi) {
    uint32_t a, b;
    asm("prmt.b32 %0, %1, 0, 0x4140;" : "=r"(a) : "r"(w));
    asm("prmt.b32 %0, %1, 0, 0x4342;" : "=r"(b) : "r"(w));
    lo = a * 0x3F80u;
    hi = b * 0x3F80u;
}
#define CPA16(dst, src) \
    asm volatile("cp.async.cg.shared.global [%0], [%1], 16;" ::"r"(dst), "l"(src) : "memory")
#define CPA_COMMIT asm volatile("cp.async.commit_group;" ::: "memory")
#define CPA_WAIT1 asm volatile("cp.async.wait_group 1;" ::: "memory")
#define CPA_WAIT0 asm volatile("cp.async.wait_group 0;" ::: "memory")
#define LDSM4(r0, r1, r2, r3, addr)                                                  \
    asm volatile("ldmatrix.sync.aligned.m8n8.x4.shared.b16 {%0,%1,%2,%3}, [%4];"     \
                 : "=r"(r0), "=r"(r1), "=r"(r2), "=r"(r3)                            \
                 : "r"(addr))
#define LDSM4T(r0, r1, r2, r3, addr)                                                   \
    asm volatile("ldmatrix.sync.aligned.m8n8.x4.trans.shared.b16 {%0,%1,%2,%3}, [%4];" \
                 : "=r"(r0), "=r"(r1), "=r"(r2), "=r"(r3)                              \
                 : "r"(addr))
#define LDSM2(r0, r1, addr)                                                          \
    asm volatile("ldmatrix.sync.aligned.m8n8.x2.shared.b16 {%0,%1}, [%2];"           \
                 : "=r"(r0), "=r"(r1)                                                \
                 : "r"(addr))
#define MMA16816(c0, c1, c2, c3, a0, a1, a2, a3, b0, b1)                             \
    asm volatile(                                                                    \
        "mma.sync.aligned.m16n8k16.row.col.f32.bf16.bf16.f32 "                       \
        "{%0,%1,%2,%3},{%4,%5,%6,%7},{%8,%9},{%0,%1,%2,%3};"                         \
        : "+f"(c0), "+f"(c1), "+f"(c2), "+f"(c3)                                     \
        : "r"(a0), "r"(a1), "r"(a2), "r"(a3), "r"(b0), "r"(b1))

// ---------------- K0: H (int32) -> int8 Ht8 [g][n] ----------------
__global__ void __launch_bounds__(256) k_conv(const int* __restrict__ H) {
    __shared__ char s[64][68];
    int g0 = blockIdx.x * 64, n0 = blockIdx.y * 64;
    int t = threadIdx.x;
#pragma unroll
    for (int i = 0; i < 4; i++) {
        int id = t + i * 256;
        int nl = id >> 4, gq = id & 15;
        int n = n0 + nl;
        char4 v = make_char4(0, 0, 0, 0);
        if (n < NT) {
            int4 h4 = *(const int4*)(H + (size_t)n * GG + g0 + gq * 4);
            v = make_char4((char)h4.x, (char)h4.y, (char)h4.z, (char)h4.w);
        }
        *(char4*)&s[nl][gq * 4] = v;
    }
    __syncthreads();
    int r = t >> 2, q = t & 3;
    char tmp[16];
#pragma unroll
    for (int k = 0; k < 16; k++) tmp[k] = s[q * 16 + k][r];
    *(uint4*)(d_Ht8 + (size_t)(g0 + r) * KCOLS + n0 + q * 16) = *(const uint4*)tmp;
}

// ---------------- K1: partial column sums ----------------
__global__ void k_colsum(const float* __restrict__ X, const float* __restrict__ uWs,
                         const float* __restrict__ iWs) {
    int part = blockIdx.y, slice = blockIdx.x;
    int Np = part ? NI : NU;
    int nstart = part ? NU : 0;
    const float* Ws = part ? iWs : uWs;
    int len = Np / 8;
    int d = threadIdx.x & 63, s = threadIdx.x >> 6;
    float acc = 0.f;
    int n_end = (slice + 1) * len;
    for (int n = slice * len + s; n < n_end; n += 4)
        acc += Ws[n] * X[(size_t)(nstart + n) * 64 + d];
    __shared__ float red[256];
    red[threadIdx.x] = acc;
    __syncthreads();
    if (s == 0)
        d_csum[(part * 8 + slice) * 64 + d] = red[d] + red[64 + d] + red[128 + d] + red[192 + d];
}

// ---------------- K2: r vector + const per part ----------------
__global__ void k_prep(const float* uWq, const float* ubq, const float* uWk, const float* ubk,
                       const float* uWs, const float* ubs, const float* iWq, const float* ibq,
                       const float* iWk, const float* ibk, const float* iWs, const float* ibs) {
    int part = blockIdx.x;
    const float* Wq = part ? iWq : uWq; const float* bq = part ? ibq : ubq;
    const float* Wk = part ? iWk : uWk; const float* bk = part ? ibk : ubk;
    const float* Ws = part ? iWs : uWs; const float* bs = part ? ibs : ubs;
    int Np = part ? NI : NU;
    int t = threadIdx.x;
    __shared__ float cS[64], tS[64], sred[64];
    float c = 0.f;
    for (int sl = 0; sl < 8; sl++) c += d_csum[(part * 8 + sl) * 64 + t];
    cS[t] = c;
    float sp = 0.f;
    for (int n = t; n < Np; n += 64) sp += Ws[n];
    sred[t] = sp;
    __syncthreads();
    for (int off = 32; off > 0; off >>= 1) {
        if (t < off) sred[t] += sred[t + off];
        __syncthreads();
    }
    float S = sred[0];
    float th = bk[t] * S;
    for (int d = 0; d < 64; d++) th += Wk[t * 64 + d] * cS[d];
    tS[t] = th;
    __syncthreads();
    float r = 0.f;
    for (int h = 0; h < 64; h++) r += Wq[h * 64 + t] * tS[h];
    d_rc[part * 65 + t] = r;
    if (t == 0) {
        float cst = bs[0];
        for (int h = 0; h < 64; h++) cst += bq[h] * tS[h];
        d_rc[part * 65 + 64] = cst;
    }
}

// ---------------- K3: per-row e, e^2, e*v ----------------
__global__ void __launch_bounds__(128) k_ev(const float* __restrict__ X, const float* uWv,
                                            const float* ubv, const float* iWv, const float* ibv) {
    __shared__ __align__(16) char shraw[(80 * 68 + 64 * 68) * 4];
    float* xs = (float*)shraw;        // [80][68]
    float* Wvs = xs + 80 * 68;        // [64][68]
    __shared__ float es[80], rs[64], bvs[64];
    __shared__ float cstS;
    int n0 = blockIdx.x * 80;
    int part = (n0 >= NU) ? 1 : 0;
    const float* Wv = part ? iWv : uWv;
    const float* bv = part ? ibv : ubv;
    int t = threadIdx.x;
#pragma unroll
    for (int i = 0; i < 10; i++) {
        int id = t + i * 128;
        int r = id >> 4, c4 = id & 15;
        *(float4*)&xs[r * 68 + c4 * 4] = *(const float4*)(X + (size_t)(n0 + r) * 64 + c4 * 4);
    }
#pragma unroll
    for (int i = 0; i < 8; i++) {
        int id = t + i * 128;
        int h = id >> 4, c4 = id & 15;
        *(float4*)&Wvs[h * 68 + c4 * 4] = *(const float4*)(Wv + h * 64 + c4 * 4);
    }
    if (t < 64) { rs[t] = d_rc[part * 65 + t]; bvs[t] = bv[t]; }
    if (t == 0) cstS = d_rc[part * 65 + 64];
    __syncthreads();
    if (t < 80) {
        float s = cstS;
#pragma unroll
        for (int d = 0; d < 64; d++) s += xs[t * 68 + d] * rs[d];
        es[t] = expf(s);
    }
    __syncthreads();
    int rg = t >> 3, hl = t & 7;
    float acc[5][8];
#pragma unroll
    for (int i = 0; i < 5; i++)
#pragma unroll
        for (int j = 0; j < 8; j++) acc[i][j] = 0.f;
#pragma unroll 4
    for (int d = 0; d < 64; d++) {
        float xv[5], wv[8];
#pragma unroll
        for (int i = 0; i < 5; i++) xv[i] = xs[(rg * 5 + i) * 68 + d];
#pragma unroll
        for (int j = 0; j < 8; j++) wv[j] = Wvs[(hl + 8 * j) * 68 + d];
#pragma unroll
        for (int i = 0; i < 5; i++)
#pragma unroll
            for (int j = 0; j < 8; j++) acc[i][j] += xv[i] * wv[j];
    }
    __syncthreads();
    __nv_bfloat16* stage = (__nv_bfloat16*)shraw;  // [66][80]
#pragma unroll
    for (int i = 0; i < 5; i++) {
        int r = rg * 5 + i;
        float e = es[r];
#pragma unroll
        for (int j = 0; j < 8; j++) {
            int h = hl + 8 * j;
            stage[h * 80 + r] = __float2bfloat16(e * (acc[i][j] + bvs[h]));
        }
    }
    if (t < 80) {
        float e = es[t];
        stage[64 * 80 + t] = __float2bfloat16(e);
        stage[65 * 80 + t] = __float2bfloat16(e * e);
        d_e2f[n0 + t] = e * e;
    }
    __syncthreads();
#pragma unroll
    for (int i = 0; i < 6; i++) {
        int id = t + i * 128;
        if (id < 660) {
            int r = id / 10, q = id % 10;
            *(uint4*)(d_EVt + (size_t)r * KCOLS + n0 + q * 8) = *(const uint4*)(stage + r * 80 + q * 8);
        }
    }
}

// ---------------- pipelined HMMA GEMM, K-tile 64, cp.async B double-buffer ----------------
// MODE 0: OUTAp[slot] = Ht(128g x K) @ EVt(80 x K)^T   (K split 4 per part)
// MODE 1: EYt = e2 * (Ht^T(64n x 4096g) @ Pt(144 x 4096g)^T)  via ldmatrix.trans
// MODE 2: MSGp[slot] = Ht(64g x K) @ EYt(144 x K)^T    (K split 4 per part)
template <int MODE>
__global__ void __launch_bounds__(256, 2) k_mma() {
    constexpr int NCP = (MODE == 0) ? 80 : 144;
    constexpr int MT = (MODE == 0) ? 128 : 64;
    constexpr int MW = MT / 4, MSUB = MW / 16, NW = NCP / 2, NSUB = NW / 8;
    constexpr int AROWS = (MODE == 0) ? 128 : 64;
    constexpr int AIT = AROWS * 4 / 256;            // 16B units of A per thread
    constexpr int BUNITS = NCP * 8;                 // 16B units of B per tile
    constexpr int BIT = (BUNITS + 255) / 256;
    constexpr int BSTG = NCP * 64;                  // halves per B stage (stride 64, swizzled)
    __shared__ __align__(16) __nv_bfloat16 sh[AROWS * 72 + 2 * BSTG];
    __nv_bfloat16* As = sh;

    const int t = threadIdx.x, lane = t & 31, warp = t >> 5;
    const int wm = warp & 3, wn = warp >> 2;
    const int mtile = blockIdx.x, split = blockIdx.y, part = blockIdx.z;
    if (MODE == 1 && part == 0 && mtile >= 125) return;

    const char* A8;
    const __nv_bfloat16* B;
    size_t Bst;
    int kc0, kc1;
    if (MODE == 1) {
        A8 = d_Ht8 + mtile * 64;
        B = d_Pt + (size_t)part * 144 * GG;
        Bst = GG;
        kc0 = 0; kc1 = 64;
    } else {
        int colbase = part ? 8000 : 0;
        A8 = d_Ht8 + (size_t)(mtile * MT) * KCOLS + colbase;
        B = ((MODE == 0) ? d_EVt : d_EYt) + colbase;
        Bst = KCOLS;
        int nch = part ? 157 : 125;
        int per = (nch + 3) >> 2;
        kc0 = split * per;
        kc1 = kc0 + per; if (kc1 > nch) kc1 = nch;
    }

    float acc[MSUB][NSUB][4];
#pragma unroll
    for (int i = 0; i < MSUB; i++)
#pragma unroll
        for (int j = 0; j < NSUB; j++)
#pragma unroll
            for (int q = 0; q < 4; q++) acc[i][j][q] = 0.f;

    const uint32_t aBase = s2u(As);
    const uint32_t bBase0 = s2u(sh + AROWS * 72);

    // B issue helper (cp.async, swizzled stride-64 rows)
    const int br = t >> 3, bc = t & 7;  // base row/chunk for i-strided issue
    auto issueB = [&](int kc, int stg) {
        uint32_t dstB = bBase0 + stg * BSTG * 2;
#pragma unroll
        for (int i = 0; i < BIT; i++) {
            int id = t + i * 256;
            if (BUNITS % 256 == 0 || id < BUNITS) {
                int r = br + i * 32, c = bc;
                uint32_t dst = dstB + (uint32_t)(r * 64 + ((c ^ (r & 7)) * 8)) * 2;
                CPA16(dst, B + (size_t)r * Bst + kc * 64 + c * 8);
            }
        }
    };

    uint4 pa[AIT];
    auto loadA = [&](int kc) {
#pragma unroll
        for (int i = 0; i < AIT; i++) {
            int id = t + i * 256;
            int r = id >> 2, c = id & 3;
            pa[i] = (MODE == 1)
                        ? *(const uint4*)(A8 + (size_t)(kc * 64 + r) * KCOLS + c * 16)
                        : *(const uint4*)(A8 + (size_t)r * KCOLS + kc * 64 + c * 16);
        }
    };

    issueB(kc0, 0);
    CPA_COMMIT;
    loadA(kc0);

    for (int kc = kc0; kc < kc1; kc++) {
        int stg = (kc - kc0) & 1;
        // commit A (unpack int8 -> bf16) into As
#pragma unroll
        for (int i = 0; i < AIT; i++) {
            int id = t + i * 256;
            int r = id >> 2, c = id & 3;
            uint32_t w[8];
            unp8(pa[i].x, w[0], w[1]);
            unp8(pa[i].y, w[2], w[3]);
            unp8(pa[i].z, w[4], w[5]);
            unp8(pa[i].w, w[6], w[7]);
            uint4* dst = (uint4*)(As + r * 72 + c * 16);
            dst[0] = make_uint4(w[0], w[1], w[2], w[3]);
            dst[1] = make_uint4(w[4], w[5], w[6], w[7]);
        }
        if (kc + 1 < kc1) issueB(kc + 1, stg ^ 1);
        CPA_COMMIT;
        if (kc + 1 < kc1) loadA(kc + 1);
        CPA_WAIT1;
        __syncthreads();

        uint32_t bsB = bBase0 + stg * BSTG * 2;
#pragma unroll
        for (int ks = 0; ks < 4; ks++) {
            uint32_t a[MSUB][4];
#pragma unroll
            for (int mi = 0; mi < MSUB; mi++) {
                if (MODE == 1) {
                    int krow = ks * 16 + ((lane >> 4) & 1) * 8 + (lane & 7);
                    int ncol = wm * 16 + ((lane >> 3) & 1) * 8;
                    uint32_t addr = aBase + (uint32_t)(krow * 72 + ncol) * 2;
                    LDSM4T(a[mi][0], a[mi][1], a[mi][2], a[mi][3], addr);
                } else {
                    uint32_t addr = aBase +
                        (uint32_t)((wm * MW + mi * 16 + (lane & 15)) * 72 + ks * 16 + (lane >> 4) * 8) * 2;
                    LDSM4(a[mi][0], a[mi][1], a[mi][2], a[mi][3], addr);
                }
            }
            uint32_t b[NSUB][2];
#pragma unroll
            for (int np = 0; np < NSUB / 2; np++) {
                int r = wn * NW + np * 16 + ((lane >> 4) & 1) * 8 + (lane & 7);
                int ch = ks * 2 + ((lane >> 3) & 1);
                uint32_t addr = bsB + (uint32_t)(r * 64 + ((ch ^ (r & 7)) * 8)) * 2;
                LDSM4(b[2 * np][0], b[2 * np][1], b[2 * np + 1][0], b[2 * np + 1][1], addr);
            }
            if (NSUB & 1) {
                int r = wn * NW + (NSUB - 1) * 8 + (lane & 7);
                int ch = ks * 2 + ((lane >> 3) & 1);
                uint32_t addr = bsB + (uint32_t)(r * 64 + ((ch ^ (r & 7)) * 8)) * 2;
                LDSM2(b[NSUB - 1][0], b[NSUB - 1][1], addr);
            }
#pragma unroll
            for (int mi = 0; mi < MSUB; mi++)
#pragma unroll
                for (int ni = 0; ni < NSUB; ni++)
                    MMA16816(acc[mi][ni][0], acc[mi][ni][1], acc[mi][ni][2], acc[mi][ni][3],
                             a[mi][0], a[mi][1], a[mi][2], a[mi][3], b[ni][0], b[ni][1]);
        }
        __syncthreads();
    }
    CPA_WAIT0;

    if (MODE != 1) {
        float* outp = ((MODE == 0) ? d_OUTAp : d_MSGp) + (size_t)(split * 2 + part) * GG * NCP;
#pragma unroll
        for (int mi = 0; mi < MSUB; mi++) {
            int gr = mtile * MT + wm * MW + mi * 16 + (lane >> 2);
#pragma unroll
            for (int ni = 0; ni < NSUB; ni++) {
                int col = wn * NW + ni * 8 + (lane & 3) * 2;
                *(float2*)&outp[(size_t)gr * NCP + col] = make_float2(acc[mi][ni][0], acc[mi][ni][1]);
                *(float2*)&outp[(size_t)(gr + 8) * NCP + col] = make_float2(acc[mi][ni][2], acc[mi][ni][3]);
            }
        }
    } else {
        __nv_bfloat16* stage = sh;  // [144][72]
        int nbase_glob = (part ? 8000 : 0) + mtile * 64;
        int rloc0 = wm * 16 + (lane >> 2), rloc1 = rloc0 + 8;
        float e2a = d_e2f[nbase_glob + rloc0];
        float e2b = d_e2f[nbase_glob + rloc1];
#pragma unroll
        for (int ni = 0; ni < NSUB; ni++) {
            int col = wn * NW + ni * 8 + (lane & 3) * 2;
            stage[(col + 0) * 72 + rloc0] = __float2bfloat16(acc[0][ni][0] * e2a);
            stage[(col + 1) * 72 + rloc0] = __float2bfloat16(acc[0][ni][1] * e2a);
            stage[(col + 0) * 72 + rloc1] = __float2bfloat16(acc[0][ni][2] * e2b);
            stage[(col + 1) * 72 + rloc1] = __float2bfloat16(acc[0][ni][3] * e2b);
        }
        __syncthreads();
        int Np = part ? NI : NU;
        int colb = part ? 8000 : 0;
#pragma unroll
        for (int i = 0; i < 5; i++) {
            int id = t + i * 256;
            if (id < 144 * 8) {
                int r = id >> 3, q = id & 7;
                int nb = mtile * 64 + q * 8;
                if (nb + 8 <= Np) {
                    *(uint4*)(d_EYt + (size_t)r * KCOLS + colb + nb) = *(const uint4*)(stage + r * 72 + q * 8);
                } else if (nb < Np) {
                    for (int e = 0; e < 8 && nb + e < Np; e++)
                        d_EYt[(size_t)r * KCOLS + colb + nb + e] = stage[r * 72 + q * 8 + e];
                }
            }
        }
    }
}

// ---------------- K5: reduce pass A, compute P / GF ----------------
__global__ void __launch_bounds__(256) k_groups() {
    __shared__ float sm[2][32][80];
    __shared__ float izS[2][32], invS[32];
    int t = threadIdx.x;
    int g0 = blockIdx.x * 32;
    for (int part = 0; part < 2; part++) {
        float r[10];
#pragma unroll
        for (int j = 0; j < 10; j++) r[j] = 0.f;
        for (int s = 0; s < 4; s++) {
            const float* base = d_OUTAp + ((size_t)(s * 2 + part) * GG + g0) * 80;
#pragma unroll
            for (int j = 0; j < 10; j++) r[j] += base[t + j * 256];
        }
#pragma unroll
        for (int j = 0; j < 10; j++) {
            int idx = t + j * 256;
            sm[part][idx / 80][idx % 80] = r[j];
        }
    }
    __syncthreads();
    if (t < 32) {
        int g = t;
        float Zu = sm[0][g][64], S2u = sm[0][g][65];
        float Zi = sm[1][g][64], S2i = sm[1][g][65];
        float izu = Zu > 0.f ? 1.f / Zu : 0.f;
        float izi = Zi > 0.f ? 1.f / Zi : 0.f;
        float n2 = S2u * izu * izu + S2i * izi * izi;
        float nn = sqrtf(n2);
        float invn = nn > 0.f ? 1.f / nn : 0.f;
        izS[0][g] = izu; izS[1][g] = izi; invS[g] = invn;
        d_iz[g0 + g] = izu; d_iz[GG + g0 + g] = izi; d_invn[g0 + g] = invn;
    }
    __syncthreads();
    for (int idx = t; idx < 32 * 129; idx += 256) {
        int g = idx & 31, c = idx >> 5;
        float gfc = 0.f;
        if (c < 128) {
            gfc = (c < 64) ? sm[0][g][c] * izS[0][g] : sm[1][g][c - 64] * izS[1][g];
            d_GF[(size_t)(g0 + g) * 128 + c] = gfc;
        }
        float inv = invS[g];
        float p0 = (c < 128) ? gfc * inv * izS[0][g] : inv * izS[0][g];
        float p1 = (c < 128) ? gfc * inv * izS[1][g] : inv * izS[1][g];
        d_Pt[(size_t)c * GG + g0 + g] = __float2bfloat16(p0);
        d_Pt[(size_t)(144 + c) * GG + g0 + g] = __float2bfloat16(p1);
    }
}

// ---------------- K8: combine, final GEMM + sigmoid ----------------
__global__ void __launch_bounds__(256) k_final(const float* __restrict__ gW,
                                               const float* __restrict__ gb,
                                               float* __restrict__ out) {
    __shared__ float gWs[64][129];
    __shared__ float aggS[4][128];
    __shared__ float idegS[4];
    int t = threadIdx.x;
    int g0 = blockIdx.x * 4;
    for (int idx = t; idx < 8192; idx += 256) gWs[idx >> 7][idx & 127] = gW[idx];
    if (t < 4) {
        int g = g0 + t;
        float mu = 0.f, mi = 0.f;
        for (int s = 0; s < 4; s++) {
            mu += d_MSGp[((size_t)(s * 2 + 0) * GG + g) * 144 + 128];
            mi += d_MSGp[((size_t)(s * 2 + 1) * GG + g) * 144 + 128];
        }
        float deg = d_invn[g] * (d_iz[g] * mu + d_iz[GG + g] * mi);
        idegS[t] = deg > 0.f ? 1.f / deg : 0.f;
    }
    __syncthreads();
    for (int idx = t; idx < 512; idx += 256) {
        int gl = idx >> 7, c = idx & 127;
        int g = g0 + gl;
        float mu = 0.f, mi = 0.f;
        for (int s = 0; s < 4; s++) {
            mu += d_MSGp[((size_t)(s * 2 + 0) * GG + g) * 144 + c];
            mi += d_MSGp[((size_t)(s * 2 + 1) * GG + g) * 144 + c];
        }
        float msg = d_invn[g] * (d_iz[g] * mu + d_iz[GG + g] * mi);
        float gf = d_GF[(size_t)g * 128 + c];
        aggS[gl][c] = 0.8f * gf + 0.2f * msg * idegS[gl];
    }
    __syncthreads();
    int gl = t >> 6, o = t & 63;
    float acc = gb[o];
#pragma unroll 8
    for (int c = 0; c < 128; c++) acc += aggS[gl][c] * gWs[o][c];
    out[(size_t)(g0 + gl) * 64 + o] = 1.f / (1.f + expf(-acc));
}

extern "C" void kernel_launch(void* const* d_in, const int* in_sizes, int n_in,
                              void* d_out, int out_size) {
    const int* H = (const int*)d_in[0];
    const float* X = (const float*)d_in[1];
    const float* uWq = (const float*)d_in[3];
    const float* ubq = (const float*)d_in[4];
    const float* uWk = (const float*)d_in[5];
    const float* ubk = (const float*)d_in[6];
    const float* uWv = (const float*)d_in[7];
    const float* ubv = (const float*)d_in[8];
    const float* uWs = (const float*)d_in[9];
    const float* ubs = (const float*)d_in[10];
    const float* iWq = (const float*)d_in[11];
    const float* ibq = (const float*)d_in[12];
    const float* iWk = (const float*)d_in[13];
    const float* ibk = (const float*)d_in[14];
    const float* iWv = (const float*)d_in[15];
    const float* ibv = (const float*)d_in[16];
    const float* iWs = (const float*)d_in[17];
    const float* ibs = (const float*)d_in[18];
    const float* gW = (const float*)d_in[19];
    const float* gb = (const float*)d_in[20];
    float* out = (float*)d_out;

    k_conv<<<dim3(64, 282), 256>>>(H);
    k_colsum<<<dim3(8, 2), 256>>>(X, uWs, iWs);
    k_prep<<<2, 64>>>(uWq, ubq, uWk, ubk, uWs, ubs, iWq, ibq, iWk, ibk, iWs, ibs);
    k_ev<<<225, 128>>>(X, uWv, ubv, iWv, ibv);
    k_mma<0><<<dim3(32, 4, 2), 256>>>();
    k_groups<<<128, 256>>>();
    k_mma<1><<<dim3(157, 1, 2), 256>>>();
    k_mma<2><<<dim3(64, 4, 2), 256>>>();
    k_final<<<1024, 256>>>(gW, gb, out);
}